// round 1
// baseline (speedup 1.0000x reference)
#include <cuda_runtime.h>

// Problem constants
#define Bsz 64
#define Lsz 200
#define Hsz 128
#define Ssz 64
#define Esz 256
#define NBsz 2
#define Kc  101
#define BLr (Bsz*Lsz)   // 12800 rows

// ---------------- scratch (device globals; no allocation allowed) -----------
__device__ float g_x   [BLr*Hsz];     // residual stream [B,L,H]
__device__ float g_ln  [BLr*Hsz];     // layernorm output
__device__ float g_xz  [BLr*2*Esz];   // in-proj output: x part [0:256), z [256:512)
__device__ float g_xc  [BLr*Esz];     // conv+silu output
__device__ float g_xsum[BLr];         // sum_e xc
__device__ float g_ssm [BLr*3*Ssz];   // xproj output: delta | B | C
__device__ float g_yc  [BLr];         // scan scalar output per (b,t)
__device__ float g_gate[BLr*Esz];     // inner-LN * silu(z)

// ---------------- helpers ---------------------------------------------------
__device__ __forceinline__ float sigmoidf_(float x){ return 1.f/(1.f+__expf(-x)); }
__device__ __forceinline__ float siluf_(float x){ return x*sigmoidf_(x); }
__device__ __forceinline__ float softplusf_(float x){ return x>20.f ? x : log1pf(__expf(x)); }

template<int NW>
__device__ __forceinline__ float block_sum(float v, float* sm){
    #pragma unroll
    for (int o=16;o;o>>=1) v += __shfl_xor_sync(0xffffffffu, v, o);
    __syncthreads();
    if ((threadIdx.x&31)==0) sm[threadIdx.x>>5] = v;
    __syncthreads();
    float s = 0.f;
    #pragma unroll
    for (int i=0;i<NW;i++) s += sm[i];
    return s;
}

// ---------------- embed: x = (item_emb[seq] + pos) * mask -------------------
__global__ void embed_kernel(const int* __restrict__ seqs, const float* __restrict__ emb,
                             const float* __restrict__ pos, float* __restrict__ x){
    int idx = blockIdx.x*blockDim.x + threadIdx.x;
    if (idx >= BLr*Hsz) return;
    int hh = idx & (Hsz-1);
    int bl = idx >> 7;
    int t  = bl % Lsz;
    int s  = seqs[bl];
    x[idx] = s ? emb[(long)s*Hsz + hh] + pos[t*Hsz + hh] : 0.f;
}

// ---------------- layernorm over width W (one row per block) ----------------
template<int W, int NW>
__global__ void ln_kernel(const float* __restrict__ x, const float* __restrict__ g,
                          const float* __restrict__ b, float* __restrict__ out){
    __shared__ float sm[NW];
    long row = blockIdx.x;
    float v = x[row*W + threadIdx.x];
    float m = block_sum<NW>(v, sm) * (1.f/W);
    float d = v - m;
    float var = block_sum<NW>(d*d, sm) * (1.f/W);
    float inv = rsqrtf(var + 1e-5f);
    out[row*W + threadIdx.x] = d*inv*g[threadIdx.x] + b[threadIdx.x];
}

// ---------------- tiled fp32 GEMM: C[M,N] = A[M,Kd]@W[Kd,N] + bias ----------
// BM=128, BN=64, BK=16, 256 threads, 8x4 microtile.
// If resid != nullptr: out = (resid + (A@W+b)) * (seqs[row]!=0)
#define GBM 128
#define GBN 64
#define GBK 16
__global__ __launch_bounds__(256) void gemm_kernel(
        const float* __restrict__ A, const float* __restrict__ W,
        const float* __restrict__ bias, float* __restrict__ C,
        int M, int Kd, int N,
        const float* __restrict__ resid, const int* __restrict__ mask_seq){
    __shared__ float As[GBK][GBM+4];
    __shared__ float Bs[GBK][GBN+4];
    int tid = threadIdx.x;
    int tx = tid & 15;       // 0..15 (N dir, 4 cols each)
    int ty = tid >> 4;       // 0..15 (M dir, 8 rows each)
    int bm = blockIdx.x * GBM;
    int bn = blockIdx.y * GBN;

    int am0 = tid >> 2;            // 0..63
    int ak  = (tid & 3) * 4;       // 0,4,8,12
    int wk  = tid >> 4;            // 0..15
    int wn  = (tid & 15) * 4;      // 0..60

    float acc[8][4];
    #pragma unroll
    for (int i=0;i<8;i++)
        #pragma unroll
        for (int j=0;j<4;j++) acc[i][j]=0.f;

    for (int kk = 0; kk < Kd; kk += GBK){
        // A tile: 128x16
        #pragma unroll
        for (int r=0;r<2;r++){
            int am = am0 + r*64;
            float4 av = *(const float4*)(A + (long)(bm+am)*Kd + kk + ak);
            As[ak+0][am]=av.x; As[ak+1][am]=av.y; As[ak+2][am]=av.z; As[ak+3][am]=av.w;
        }
        // W tile: 16x64
        float4 wv = *(const float4*)(W + (long)(kk+wk)*N + bn + wn);
        *(float4*)&Bs[wk][wn] = wv;
        __syncthreads();
        #pragma unroll
        for (int k=0;k<GBK;k++){
            float4 ra0 = *(const float4*)&As[k][ty*8];
            float4 ra1 = *(const float4*)&As[k][ty*8+4];
            float4 rb  = *(const float4*)&Bs[k][tx*4];
            float a[8] = {ra0.x,ra0.y,ra0.z,ra0.w,ra1.x,ra1.y,ra1.z,ra1.w};
            float bb[4]= {rb.x,rb.y,rb.z,rb.w};
            #pragma unroll
            for (int i=0;i<8;i++)
                #pragma unroll
                for (int j=0;j<4;j++) acc[i][j] = fmaf(a[i], bb[j], acc[i][j]);
        }
        __syncthreads();
    }
    float bv[4];
    #pragma unroll
    for (int j=0;j<4;j++) bv[j] = bias[bn + tx*4 + j];
    #pragma unroll
    for (int i=0;i<8;i++){
        int row = bm + ty*8 + i;
        if (resid){
            float msk = (mask_seq[row] != 0) ? 1.f : 0.f;
            #pragma unroll
            for (int j=0;j<4;j++){
                int col = bn + tx*4 + j;
                C[(long)row*N + col] = (resid[(long)row*N + col] + acc[i][j] + bv[j]) * msk;
            }
        } else {
            #pragma unroll
            for (int j=0;j<4;j++){
                int col = bn + tx*4 + j;
                C[(long)row*N + col] = acc[i][j] + bv[j];
            }
        }
    }
}

// ---------------- depthwise conv(k=3,pad=1) + silu + row-sum ----------------
__global__ void conv_kernel(const float* __restrict__ xz, const float* __restrict__ cw,
                            const float* __restrict__ cb, float* __restrict__ xc,
                            float* __restrict__ xsum){
    __shared__ float sm[8];
    int row = blockIdx.x;
    int t = row % Lsz;
    int e = threadIdx.x;   // 0..255
    float xm1 = (t > 0)      ? xz[(long)(row-1)*(2*Esz) + e] : 0.f;
    float x0  =                xz[(long)row    *(2*Esz) + e];
    float xp1 = (t < Lsz-1)  ? xz[(long)(row+1)*(2*Esz) + e] : 0.f;
    float v = fmaf(xm1, cw[e*3+0], fmaf(x0, cw[e*3+1], fmaf(xp1, cw[e*3+2], cb[e])));
    float s = siluf_(v);
    xc[(long)row*Esz + e] = s;
    float tot = block_sum<8>(s, sm);
    if (e == 0) xsum[row] = tot;
}

// ---------------- sequential SSM scan (state collapsed to [B,S]) ------------
__global__ __launch_bounds__(256) void scan_kernel(
        const float* __restrict__ ssm, const float* __restrict__ xsum,
        const float* __restrict__ A_log, float* __restrict__ yc){
    __shared__ float A_s[Ssz], h_s[Ssz], dB_s[Ssz], C_s[Ssz], delta_s[Ssz], prod_s[Ssz];
    __shared__ float xs_sh;
    int b = blockIdx.x;
    int tid = threadIdx.x;          // 256
    int i = tid >> 2;               // state row 0..63
    int q = tid & 3;                // j-subset

    if (tid < Ssz){
        A_s[tid] = -__expf(fminf(fmaxf(A_log[tid], -5.f), 5.f));
        h_s[tid] = 0.f;
    }
    __syncthreads();
    float Areg[16];
    #pragma unroll
    for (int jj=0;jj<16;jj++) Areg[jj] = A_s[q*16+jj];

    const float* srow = ssm + (long)b*Lsz*(3*Ssz);
    float nd=0.f, nb=0.f, nc=0.f, nxs=0.f;
    if (tid < Ssz){ nd = srow[tid]; nb = srow[Ssz+tid]; nc = srow[2*Ssz+tid]; }
    if (tid == 0) nxs = xsum[b*Lsz];

    for (int t=0; t<Lsz; t++){
        if (tid < Ssz){
            float d = softplusf_(nd);
            delta_s[tid] = d;
            dB_s[tid] = d * nb;
            C_s[tid]  = nc;
        }
        if (tid == 0) xs_sh = nxs;
        __syncthreads();                        // staging visible
        // prefetch t+1
        if (t+1 < Lsz){
            const float* nr = srow + (long)(t+1)*(3*Ssz);
            if (tid < Ssz){ nd = nr[tid]; nb = nr[Ssz+tid]; nc = nr[2*Ssz+tid]; }
            if (tid == 0) nxs = xsum[b*Lsz + t + 1];
        }
        float di = delta_s[i];
        float partial = 0.f;
        #pragma unroll
        for (int jj=0;jj<16;jj++){
            int j = q*16 + jj;
            float w = __expf(fmaxf(di * Areg[jj], -10.f));
            partial = fmaf(w, h_s[j], partial);
        }
        partial += __shfl_xor_sync(0xffffffffu, partial, 1);
        partial += __shfl_xor_sync(0xffffffffu, partial, 2);
        float hn = 0.f, pr = 0.f;
        if (q == 0){
            hn = partial + dB_s[i]*xs_sh;
            hn = fminf(fmaxf(hn, -100.f), 100.f);
            pr = hn * C_s[i];
        }
        __syncthreads();                        // all h_s reads done
        if (q == 0){ h_s[i] = hn; prod_s[i] = pr; }
        __syncthreads();                        // h_s/prod_s writes visible
        if (tid < 32){
            float v = prod_s[tid] + prod_s[tid+32];
            #pragma unroll
            for (int o=16;o;o>>=1) v += __shfl_xor_sync(0xffffffffu, v, o);
            if (tid == 0) yc[b*Lsz + t] = v;
        }
    }
}

// ---------------- y = LN_E(yc + D*xc) * silu(z) -----------------------------
__global__ void gate_kernel(const float* __restrict__ xc, const float* __restrict__ yc,
                            const float* __restrict__ xz, const float* __restrict__ Dp,
                            const float* __restrict__ ig, const float* __restrict__ ib,
                            float* __restrict__ out){
    __shared__ float sm[8];
    int row = blockIdx.x;
    int e = threadIdx.x;  // 0..255
    float v = yc[row] + Dp[e] * xc[(long)row*Esz + e];
    float m = block_sum<8>(v, sm) * (1.f/Esz);
    float d = v - m;
    float var = block_sum<8>(d*d, sm) * (1.f/Esz);
    float inv = rsqrtf(var + 1e-5f);
    float z = xz[(long)row*(2*Esz) + Esz + e];
    out[(long)row*Esz + e] = (d*inv*ig[e] + ib[e]) * siluf_(z);
}

// ---------------- final LN (last step only) + candidate logits --------------
__global__ void final_kernel(const float* __restrict__ x, const float* __restrict__ fg,
                             const float* __restrict__ fb, const int* __restrict__ idxs,
                             const float* __restrict__ emb, float* __restrict__ out){
    __shared__ float sm[4];
    __shared__ float xf[Hsz];
    int b = blockIdx.x;
    int tid = threadIdx.x;  // 128
    const float* xr = x + (long)(b*Lsz + Lsz-1)*Hsz;
    float v = xr[tid];
    float m = block_sum<4>(v, sm) * (1.f/Hsz);
    float d = v - m;
    float var = block_sum<4>(d*d, sm) * (1.f/Hsz);
    float inv = rsqrtf(var + 1e-5f);
    xf[tid] = d*inv*fg[tid] + fb[tid];
    __syncthreads();
    int w = tid >> 5, l = tid & 31;
    for (int k = w; k < Kc; k += 4){
        int idx = idxs[b*Kc + k];
        const float* er = emb + (long)idx*Hsz;
        float acc = 0.f;
        #pragma unroll
        for (int r=0;r<4;r++) acc = fmaf(xf[l+32*r], er[l+32*r], acc);
        #pragma unroll
        for (int o=16;o;o>>=1) acc += __shfl_xor_sync(0xffffffffu, acc, o);
        if (l == 0) out[b*Kc + k] = acc;
    }
}

// ---------------- host orchestration ----------------------------------------
extern "C" void kernel_launch(void* const* d_in, const int* in_sizes, int n_in,
                              void* d_out, int out_size){
    const int*   seqs  = (const int*)  d_in[0];
    const int*   idxs  = (const int*)  d_in[1];
    const float* emb   = (const float*)d_in[2];
    const float* pos   = (const float*)d_in[3];
    const float* blkg  = (const float*)d_in[4];
    const float* blkb  = (const float*)d_in[5];
    const float* in_w  = (const float*)d_in[6];
    const float* in_b  = (const float*)d_in[7];
    const float* convw = (const float*)d_in[8];
    const float* convb = (const float*)d_in[9];
    const float* xp_w  = (const float*)d_in[10];
    const float* xp_b  = (const float*)d_in[11];
    const float* A_log = (const float*)d_in[12];
    const float* Dp    = (const float*)d_in[13];
    const float* out_w = (const float*)d_in[14];
    const float* out_b = (const float*)d_in[15];
    const float* ilg   = (const float*)d_in[16];
    const float* ilb   = (const float*)d_in[17];
    const float* flg   = (const float*)d_in[18];
    const float* flb   = (const float*)d_in[19];
    float* logits = (float*)d_out;

    float *x,*ln,*xz,*xc,*xs,*ssm,*yc,*gate;
    cudaGetSymbolAddress((void**)&x,    g_x);
    cudaGetSymbolAddress((void**)&ln,   g_ln);
    cudaGetSymbolAddress((void**)&xz,   g_xz);
    cudaGetSymbolAddress((void**)&xc,   g_xc);
    cudaGetSymbolAddress((void**)&xs,   g_xsum);
    cudaGetSymbolAddress((void**)&ssm,  g_ssm);
    cudaGetSymbolAddress((void**)&yc,   g_yc);
    cudaGetSymbolAddress((void**)&gate, g_gate);

    embed_kernel<<<(BLr*Hsz + 255)/256, 256>>>(seqs, emb, pos, x);

    for (int blk = 0; blk < NBsz; blk++){
        ln_kernel<Hsz,4><<<BLr, Hsz>>>(x, blkg + blk*Hsz, blkb + blk*Hsz, ln);

        gemm_kernel<<<dim3(BLr/GBM, (2*Esz)/GBN), 256>>>(
            ln, in_w + (long)blk*Hsz*2*Esz, in_b + blk*2*Esz, xz,
            BLr, Hsz, 2*Esz, nullptr, nullptr);

        conv_kernel<<<BLr, Esz>>>(xz, convw + blk*Esz*3, convb + blk*Esz, xc, xs);

        gemm_kernel<<<dim3(BLr/GBM, (3*Ssz)/GBN), 256>>>(
            xc, xp_w + (long)blk*Esz*3*Ssz, xp_b + blk*3*Ssz, ssm,
            BLr, Esz, 3*Ssz, nullptr, nullptr);

        scan_kernel<<<Bsz, 256>>>(ssm, xs, A_log + blk*Ssz, yc);

        gate_kernel<<<BLr, Esz>>>(xc, yc, xz, Dp + blk*Esz, ilg + blk*Esz, ilb + blk*Esz, gate);

        gemm_kernel<<<dim3(BLr/GBM, Hsz/GBN), 256>>>(
            gate, out_w + (long)blk*Esz*Hsz, out_b + blk*Hsz, x,
            BLr, Esz, Hsz, x, seqs);
    }

    final_kernel<<<Bsz, Hsz>>>(x, flg, flb, idxs, emb, logits);
}

// round 9
// speedup vs baseline: 1.1732x; 1.1732x over previous
#include <cuda_runtime.h>
#include <cstdint>

// Problem constants
#define Bsz 64
#define Lsz 200
#define Hsz 128
#define Ssz 64
#define Esz 256
#define NBsz 2
#define Kc  101
#define BLr (Bsz*Lsz)   // 12800 rows

// ---------------- scratch (device globals; no allocation allowed) -----------
__device__ float g_x   [BLr*Hsz];     // residual stream [B,L,H]
__device__ float g_ln  [BLr*Hsz];     // layernorm output
__device__ float g_xz  [BLr*2*Esz];   // in-proj output: x part [0:256), z [256:512)
__device__ float g_xc  [BLr*Esz];     // conv+silu output
__device__ float g_xsum[BLr];         // sum_e xc
__device__ float g_ssm [BLr*3*Ssz];   // xproj output: delta | B | C
__device__ float g_yc  [BLr];         // scan scalar output per (b,t)
__device__ float g_gate[BLr*Esz];     // inner-LN * silu(z)

// ---------------- helpers ---------------------------------------------------
__device__ __forceinline__ float sigmoidf_(float x){ return 1.f/(1.f+__expf(-x)); }
__device__ __forceinline__ float siluf_(float x){ return x*sigmoidf_(x); }
__device__ __forceinline__ float softplusf_(float x){ return x>20.f ? x : log1pf(__expf(x)); }

template<int NW>
__device__ __forceinline__ float block_sum(float v, float* sm){
    #pragma unroll
    for (int o=16;o;o>>=1) v += __shfl_xor_sync(0xffffffffu, v, o);
    __syncthreads();
    if ((threadIdx.x&31)==0) sm[threadIdx.x>>5] = v;
    __syncthreads();
    float s = 0.f;
    #pragma unroll
    for (int i=0;i<NW;i++) s += sm[i];
    return s;
}

__device__ __forceinline__ float warp_sum(float v){
    #pragma unroll
    for (int o=16;o;o>>=1) v += __shfl_xor_sync(0xffffffffu, v, o);
    return v;
}

__device__ __forceinline__ void tf32split(float v, uint32_t& hi, uint32_t& lo){
    uint32_t h; asm("cvt.rna.tf32.f32 %0, %1;" : "=r"(h) : "f"(v));
    float r = v - __uint_as_float(h);
    uint32_t l; asm("cvt.rna.tf32.f32 %0, %1;" : "=r"(l) : "f"(r));
    hi = h; lo = l;
}

__device__ __forceinline__ void mma16n8k8(float* c, const uint32_t* a, const uint32_t* b){
    asm volatile("mma.sync.aligned.m16n8k8.row.col.f32.tf32.tf32.f32 "
        "{%0,%1,%2,%3}, {%4,%5,%6,%7}, {%8,%9}, {%0,%1,%2,%3};"
        : "+f"(c[0]),"+f"(c[1]),"+f"(c[2]),"+f"(c[3])
        : "r"(a[0]),"r"(a[1]),"r"(a[2]),"r"(a[3]), "r"(b[0]),"r"(b[1]));
}

// ---------------- embed: x = (item_emb[seq] + pos) * mask, float4 ----------
__global__ void embed_kernel(const int* __restrict__ seqs, const float* __restrict__ emb,
                             const float* __restrict__ pos, float* __restrict__ x){
    int idx = blockIdx.x*blockDim.x + threadIdx.x;   // one thread = 4 floats
    if (idx >= BLr*(Hsz/4)) return;
    int h4 = (idx & 31) * 4;       // 0..124
    int bl = idx >> 5;
    int t  = bl % Lsz;
    int s  = seqs[bl];
    float4 o;
    if (s){
        float4 e = *(const float4*)(emb + (long)s*Hsz + h4);
        float4 p = *(const float4*)(pos + t*Hsz + h4);
        o = make_float4(e.x+p.x, e.y+p.y, e.z+p.z, e.w+p.w);
    } else {
        o = make_float4(0.f,0.f,0.f,0.f);
    }
    *(float4*)(x + (long)bl*Hsz + h4) = o;
}

// ---------------- layernorm H=128, warp-per-row (4 rows / 128-thr block) ----
__global__ void ln128_kernel(const float* __restrict__ x, const float* __restrict__ g,
                             const float* __restrict__ b, float* __restrict__ out){
    int row  = blockIdx.x*4 + (threadIdx.x >> 5);
    int lane = threadIdx.x & 31;
    float4 v = *(const float4*)(x + (long)row*Hsz + lane*4);
    float m = warp_sum(v.x + v.y + v.z + v.w) * (1.f/Hsz);
    float4 d = make_float4(v.x-m, v.y-m, v.z-m, v.w-m);
    float var = warp_sum(d.x*d.x + d.y*d.y + d.z*d.z + d.w*d.w) * (1.f/Hsz);
    float inv = rsqrtf(var + 1e-5f);
    float4 gg = *(const float4*)(g + lane*4);
    float4 bb = *(const float4*)(b + lane*4);
    float4 o;
    o.x = d.x*inv*gg.x + bb.x;
    o.y = d.y*inv*gg.y + bb.y;
    o.z = d.z*inv*gg.z + bb.z;
    o.w = d.w*inv*gg.w + bb.w;
    *(float4*)(out + (long)row*Hsz + lane*4) = o;
}

// ---------------- 3xTF32 tensor-core GEMM: C[M,N]=A[M,Kd]@W[Kd,N]+bias ------
// BM=128, BN=64, BK=32, 256 threads = 8 warps (4M x 2N), warp tile 32x32.
// If resid != nullptr: out = (resid + (A@W+b)) * (seqs[row]!=0)
#define GBM 128
#define GBN 64
#define GBK 32
#define ASTR 36   // A smem stride (floats): bank = 4g+tg -> conflict-free
#define BSTR 72   // B smem stride (floats): bank = 8tg+g -> conflict-free

__global__ __launch_bounds__(256) void gemm_tf32_kernel(
        const float* __restrict__ A, const float* __restrict__ W,
        const float* __restrict__ bias, float* __restrict__ C,
        int M, int Kd, int N,
        const float* __restrict__ resid, const int* __restrict__ mask_seq){
    __shared__ float As[GBM][ASTR];   // 18.4 KB
    __shared__ float Bs[GBK][BSTR];   //  9.2 KB
    int tid  = threadIdx.x;
    int lane = tid & 31;
    int w    = tid >> 5;
    int warpM = w >> 1;               // 0..3
    int warpN = w & 1;                // 0..1
    int g  = lane >> 2;               // 0..7
    int tg = lane & 3;                // 0..3
    int bm = blockIdx.x * GBM;
    int bn = blockIdx.y * GBN;

    // global-load mapping
    int arow = tid >> 3;              // 0..31 (plus +32r)
    int acol = (tid & 7) * 4;         // 0..28
    int brow = tid >> 3;              // 0..31
    int bcol = (tid & 7) * 4;         // 0..28 (and +32)

    float acc[2][4][4];
    #pragma unroll
    for (int mi=0;mi<2;mi++)
        #pragma unroll
        for (int ni=0;ni<4;ni++)
            #pragma unroll
            for (int c=0;c<4;c++) acc[mi][ni][c]=0.f;

    // prefetch tile 0
    float4 pa[4], pb[2];
    #pragma unroll
    for (int r=0;r<4;r++)
        pa[r] = *(const float4*)(A + (long)(bm + arow + 32*r)*Kd + acol);
    pb[0] = *(const float4*)(W + (long)brow*N + bn + bcol);
    pb[1] = *(const float4*)(W + (long)brow*N + bn + bcol + 32);

    for (int kt = 0; kt < Kd; kt += GBK){
        // commit prefetched tile to SMEM
        #pragma unroll
        for (int r=0;r<4;r++)
            *(float4*)&As[arow + 32*r][acol] = pa[r];
        *(float4*)&Bs[brow][bcol]      = pb[0];
        *(float4*)&Bs[brow][bcol + 32] = pb[1];
        __syncthreads();

        // prefetch next tile
        if (kt + GBK < Kd){
            #pragma unroll
            for (int r=0;r<4;r++)
                pa[r] = *(const float4*)(A + (long)(bm + arow + 32*r)*Kd + kt + GBK + acol);
            pb[0] = *(const float4*)(W + (long)(kt + GBK + brow)*N + bn + bcol);
            pb[1] = *(const float4*)(W + (long)(kt + GBK + brow)*N + bn + bcol + 32);
        }

        #pragma unroll
        for (int k8 = 0; k8 < GBK/8; k8++){
            int k0 = k8*8;
            // A fragments (2 m-tiles), split hi/lo
            uint32_t ah[2][4], al[2][4];
            #pragma unroll
            for (int mi=0;mi<2;mi++){
                int r0 = warpM*32 + mi*16 + g;
                float v0 = As[r0    ][k0 + tg    ];
                float v1 = As[r0 + 8][k0 + tg    ];
                float v2 = As[r0    ][k0 + tg + 4];
                float v3 = As[r0 + 8][k0 + tg + 4];
                tf32split(v0, ah[mi][0], al[mi][0]);
                tf32split(v1, ah[mi][1], al[mi][1]);
                tf32split(v2, ah[mi][2], al[mi][2]);
                tf32split(v3, ah[mi][3], al[mi][3]);
            }
            // B fragments (4 n-tiles), split hi/lo
            uint32_t bh[4][2], bl[4][2];
            #pragma unroll
            for (int ni=0;ni<4;ni++){
                int c0 = warpN*32 + ni*8 + g;
                float u0 = Bs[k0 + tg    ][c0];
                float u1 = Bs[k0 + tg + 4][c0];
                tf32split(u0, bh[ni][0], bl[ni][0]);
                tf32split(u1, bh[ni][1], bl[ni][1]);
            }
            #pragma unroll
            for (int mi=0;mi<2;mi++)
                #pragma unroll
                for (int ni=0;ni<4;ni++){
                    mma16n8k8(acc[mi][ni], ah[mi], bh[ni]);
                    mma16n8k8(acc[mi][ni], ah[mi], bl[ni]);
                    mma16n8k8(acc[mi][ni], al[mi], bh[ni]);
                }
        }
        __syncthreads();
    }

    // epilogue
    #pragma unroll
    for (int mi=0;mi<2;mi++){
        int r0 = bm + warpM*32 + mi*16 + g;
        #pragma unroll
        for (int ni=0;ni<4;ni++){
            int col = bn + warpN*32 + ni*8 + 2*tg;
            float b0 = bias[col], b1 = bias[col+1];
            float v00 = acc[mi][ni][0] + b0, v01 = acc[mi][ni][1] + b1;
            float v10 = acc[mi][ni][2] + b0, v11 = acc[mi][ni][3] + b1;
            if (resid){
                float m0 = (mask_seq[r0]   != 0) ? 1.f : 0.f;
                float m1 = (mask_seq[r0+8] != 0) ? 1.f : 0.f;
                const float* rr0 = resid + (long)r0*N + col;
                const float* rr1 = resid + (long)(r0+8)*N + col;
                v00 = (rr0[0] + v00)*m0; v01 = (rr0[1] + v01)*m0;
                v10 = (rr1[0] + v10)*m1; v11 = (rr1[1] + v11)*m1;
            }
            *(float2*)(C + (long)r0*N + col)     = make_float2(v00, v01);
            *(float2*)(C + (long)(r0+8)*N + col) = make_float2(v10, v11);
        }
    }
}

// ---------------- depthwise conv(k=3,pad=1)+silu+row-sum, warp-per-row ------
__global__ void conv_kernel(const float* __restrict__ xz, const float* __restrict__ cw,
                            const float* __restrict__ cb, float* __restrict__ xc,
                            float* __restrict__ xsum){
    int row  = blockIdx.x*4 + (threadIdx.x >> 5);
    int lane = threadIdx.x & 31;
    int t = row % Lsz;
    int e0 = lane*8;
    const float* rp = xz + (long)row*(2*Esz) + e0;
    float4 c0a = *(const float4*)(rp);
    float4 c0b = *(const float4*)(rp + 4);
    float4 cma, cmb, cpa, cpb;
    if (t > 0){ cma = *(const float4*)(rp - 2*Esz); cmb = *(const float4*)(rp - 2*Esz + 4); }
    else      { cma = make_float4(0.f,0.f,0.f,0.f); cmb = cma; }
    if (t < Lsz-1){ cpa = *(const float4*)(rp + 2*Esz); cpb = *(const float4*)(rp + 2*Esz + 4); }
    else          { cpa = make_float4(0.f,0.f,0.f,0.f); cpb = cpa; }
    float xm[8] = {cma.x,cma.y,cma.z,cma.w, cmb.x,cmb.y,cmb.z,cmb.w};
    float x0[8] = {c0a.x,c0a.y,c0a.z,c0a.w, c0b.x,c0b.y,c0b.z,c0b.w};
    float xp[8] = {cpa.x,cpa.y,cpa.z,cpa.w, cpb.x,cpb.y,cpb.z,cpb.w};
    float s[8];
    float tot = 0.f;
    #pragma unroll
    for (int i=0;i<8;i++){
        int e = e0 + i;
        float v = fmaf(xm[i], cw[e*3+0], fmaf(x0[i], cw[e*3+1], fmaf(xp[i], cw[e*3+2], cb[e])));
        s[i] = siluf_(v);
        tot += s[i];
    }
    tot = warp_sum(tot);
    if (lane == 0) xsum[row] = tot;
    float* op = xc + (long)row*Esz + e0;
    *(float4*)(op)     = make_float4(s[0],s[1],s[2],s[3]);
    *(float4*)(op + 4) = make_float4(s[4],s[5],s[6],s[7]);
}

// ---------------- sequential SSM scan (state collapsed to [B,S]) ------------
__global__ __launch_bounds__(256) void scan_kernel(
        const float* __restrict__ ssm, const float* __restrict__ xsum,
        const float* __restrict__ A_log, float* __restrict__ yc){
    __shared__ float A_s[Ssz], h_s[Ssz], dB_s[Ssz], C_s[Ssz], delta_s[Ssz], prod_s[Ssz];
    __shared__ float xs_sh;
    int b = blockIdx.x;
    int tid = threadIdx.x;          // 256
    int i = tid >> 2;               // state row 0..63
    int q = tid & 3;                // j-subset

    if (tid < Ssz){
        A_s[tid] = -__expf(fminf(fmaxf(A_log[tid], -5.f), 5.f));
        h_s[tid] = 0.f;
    }
    __syncthreads();
    float Areg[16];
    #pragma unroll
    for (int jj=0;jj<16;jj++) Areg[jj] = A_s[q*16+jj];

    const float* srow = ssm + (long)b*Lsz*(3*Ssz);
    float nd=0.f, nb=0.f, nc=0.f, nxs=0.f;
    if (tid < Ssz){ nd = srow[tid]; nb = srow[Ssz+tid]; nc = srow[2*Ssz+tid]; }
    if (tid == 0) nxs = xsum[b*Lsz];

    for (int t=0; t<Lsz; t++){
        if (tid < Ssz){
            float d = softplusf_(nd);
            delta_s[tid] = d;
            dB_s[tid] = d * nb;
            C_s[tid]  = nc;
        }
        if (tid == 0) xs_sh = nxs;
        __syncthreads();                        // staging visible
        // prefetch t+1
        if (t+1 < Lsz){
            const float* nr = srow + (long)(t+1)*(3*Ssz);
            if (tid < Ssz){ nd = nr[tid]; nb = nr[Ssz+tid]; nc = nr[2*Ssz+tid]; }
            if (tid == 0) nxs = xsum[b*Lsz + t + 1];
        }
        float di = delta_s[i];
        float partial = 0.f;
        #pragma unroll
        for (int jj=0;jj<16;jj++){
            int j = q*16 + jj;
            float w = __expf(fmaxf(di * Areg[jj], -10.f));
            partial = fmaf(w, h_s[j], partial);
        }
        partial += __shfl_xor_sync(0xffffffffu, partial, 1);
        partial += __shfl_xor_sync(0xffffffffu, partial, 2);
        float hn = 0.f, pr = 0.f;
        if (q == 0){
            hn = partial + dB_s[i]*xs_sh;
            hn = fminf(fmaxf(hn, -100.f), 100.f);
            pr = hn * C_s[i];
        }
        __syncthreads();                        // all h_s reads done
        if (q == 0){ h_s[i] = hn; prod_s[i] = pr; }
        __syncthreads();                        // h_s/prod_s writes visible
        if (tid < 32){
            float v = prod_s[tid] + prod_s[tid+32];
            #pragma unroll
            for (int o=16;o;o>>=1) v += __shfl_xor_sync(0xffffffffu, v, o);
            if (tid == 0) yc[b*Lsz + t] = v;
        }
    }
}

// ---------------- y = LN_E(yc + D*xc) * silu(z), warp-per-row ---------------
__global__ void gate_kernel(const float* __restrict__ xc, const float* __restrict__ yc,
                            const float* __restrict__ xz, const float* __restrict__ Dp,
                            const float* __restrict__ ig, const float* __restrict__ ib,
                            float* __restrict__ out){
    int row  = blockIdx.x*4 + (threadIdx.x >> 5);
    int lane = threadIdx.x & 31;
    float ycr = yc[row];
    // 8 elems per lane: [lane*8, lane*8+8)
    float4 a0 = *(const float4*)(xc + (long)row*Esz + lane*8);
    float4 a1 = *(const float4*)(xc + (long)row*Esz + lane*8 + 4);
    float4 d0 = *(const float4*)(Dp + lane*8);
    float4 d1 = *(const float4*)(Dp + lane*8 + 4);
    float v[8];
    v[0]=ycr+d0.x*a0.x; v[1]=ycr+d0.y*a0.y; v[2]=ycr+d0.z*a0.z; v[3]=ycr+d0.w*a0.w;
    v[4]=ycr+d1.x*a1.x; v[5]=ycr+d1.y*a1.y; v[6]=ycr+d1.z*a1.z; v[7]=ycr+d1.w*a1.w;
    float s = 0.f;
    #pragma unroll
    for (int i=0;i<8;i++) s += v[i];
    float m = warp_sum(s) * (1.f/Esz);
    float vs = 0.f;
    #pragma unroll
    for (int i=0;i<8;i++){ v[i] -= m; vs += v[i]*v[i]; }
    float var = warp_sum(vs) * (1.f/Esz);
    float inv = rsqrtf(var + 1e-5f);
    float4 g0 = *(const float4*)(ig + lane*8);
    float4 g1 = *(const float4*)(ig + lane*8 + 4);
    float4 b0 = *(const float4*)(ib + lane*8);
    float4 b1 = *(const float4*)(ib + lane*8 + 4);
    float4 z0 = *(const float4*)(xz + (long)row*(2*Esz) + Esz + lane*8);
    float4 z1 = *(const float4*)(xz + (long)row*(2*Esz) + Esz + lane*8 + 4);
    float4 o0, o1;
    o0.x = (v[0]*inv*g0.x + b0.x) * siluf_(z0.x);
    o0.y = (v[1]*inv*g0.y + b0.y) * siluf_(z0.y);
    o0.z = (v[2]*inv*g0.z + b0.z) * siluf_(z0.z);
    o0.w = (v[3]*inv*g0.w + b0.w) * siluf_(z0.w);
    o1.x = (v[4]*inv*g1.x + b1.x) * siluf_(z1.x);
    o1.y = (v[5]*inv*g1.y + b1.y) * siluf_(z1.y);
    o1.z = (v[6]*inv*g1.z + b1.z) * siluf_(z1.z);
    o1.w = (v[7]*inv*g1.w + b1.w) * siluf_(z1.w);
    *(float4*)(out + (long)row*Esz + lane*8)     = o0;
    *(float4*)(out + (long)row*Esz + lane*8 + 4) = o1;
}

// ---------------- final LN (last step only) + candidate logits --------------
__global__ void final_kernel(const float* __restrict__ x, const float* __restrict__ fg,
                             const float* __restrict__ fb, const int* __restrict__ idxs,
                             const float* __restrict__ emb, float* __restrict__ out){
    __shared__ float sm[4];
    __shared__ float xf[Hsz];
    int b = blockIdx.x;
    int tid = threadIdx.x;  // 128
    const float* xr = x + (long)(b*Lsz + Lsz-1)*Hsz;
    float v = xr[tid];
    float m = block_sum<4>(v, sm) * (1.f/Hsz);
    float d = v - m;
    float var = block_sum<4>(d*d, sm) * (1.f/Hsz);
    float inv = rsqrtf(var + 1e-5f);
    xf[tid] = d*inv*fg[tid] + fb[tid];
    __syncthreads();
    int w = tid >> 5, l = tid & 31;
    for (int k = w; k < Kc; k += 4){
        int idx = idxs[b*Kc + k];
        const float* er = emb + (long)idx*Hsz;
        float acc = 0.f;
        #pragma unroll
        for (int r=0;r<4;r++) acc = fmaf(xf[l+32*r], er[l+32*r], acc);
        #pragma unroll
        for (int o=16;o;o>>=1) acc += __shfl_xor_sync(0xffffffffu, acc, o);
        if (l == 0) out[b*Kc + k] = acc;
    }
}

// ---------------- host orchestration ----------------------------------------
extern "C" void kernel_launch(void* const* d_in, const int* in_sizes, int n_in,
                              void* d_out, int out_size){
    const int*   seqs  = (const int*)  d_in[0];
    const int*   idxs  = (const int*)  d_in[1];
    const float* emb   = (const float*)d_in[2];
    const float* pos   = (const float*)d_in[3];
    const float* blkg  = (const float*)d_in[4];
    const float* blkb  = (const float*)d_in[5];
    const float* in_w  = (const float*)d_in[6];
    const float* in_b  = (const float*)d_in[7];
    const float* convw = (const float*)d_in[8];
    const float* convb = (const float*)d_in[9];
    const float* xp_w  = (const float*)d_in[10];
    const float* xp_b  = (const float*)d_in[11];
    const float* A_log = (const float*)d_in[12];
    const float* Dp    = (const float*)d_in[13];
    const float* out_w = (const float*)d_in[14];
    const float* out_b = (const float*)d_in[15];
    const float* ilg   = (const float*)d_in[16];
    const float* ilb   = (const float*)d_in[17];
    const float* flg   = (const float*)d_in[18];
    const float* flb   = (const float*)d_in[19];
    float* logits = (float*)d_out;

    float *x,*ln,*xz,*xc,*xs,*ssm,*yc,*gate;
    cudaGetSymbolAddress((void**)&x,    g_x);
    cudaGetSymbolAddress((void**)&ln,   g_ln);
    cudaGetSymbolAddress((void**)&xz,   g_xz);
    cudaGetSymbolAddress((void**)&xc,   g_xc);
    cudaGetSymbolAddress((void**)&xs,   g_xsum);
    cudaGetSymbolAddress((void**)&ssm,  g_ssm);
    cudaGetSymbolAddress((void**)&yc,   g_yc);
    cudaGetSymbolAddress((void**)&gate, g_gate);

    embed_kernel<<<(BLr*(Hsz/4) + 255)/256, 256>>>(seqs, emb, pos, x);

    for (int blk = 0; blk < NBsz; blk++){
        ln128_kernel<<<BLr/4, 128>>>(x, blkg + blk*Hsz, blkb + blk*Hsz, ln);

        gemm_tf32_kernel<<<dim3(BLr/GBM, (2*Esz)/GBN), 256>>>(
            ln, in_w + (long)blk*Hsz*2*Esz, in_b + blk*2*Esz, xz,
            BLr, Hsz, 2*Esz, nullptr, nullptr);

        conv_kernel<<<BLr/4, 128>>>(xz, convw + blk*Esz*3, convb + blk*Esz, xc, xs);

        gemm_tf32_kernel<<<dim3(BLr/GBM, (3*Ssz)/GBN), 256>>>(
            xc, xp_w + (long)blk*Esz*3*Ssz, xp_b + blk*3*Ssz, ssm,
            BLr, Esz, 3*Ssz, nullptr, nullptr);

        scan_kernel<<<Bsz, 256>>>(ssm, xs, A_log + blk*Ssz, yc);

        gate_kernel<<<BLr/4, 128>>>(xc, yc, xz, Dp + blk*Esz, ilg + blk*Esz, ilb + blk*Esz, gate);

        gemm_tf32_kernel<<<dim3(BLr/GBM, Hsz/GBN), 256>>>(
            gate, out_w + (long)blk*Esz*Hsz, out_b + blk*Hsz, x,
            BLr, Esz, Hsz, x, seqs);
    }

    final_kernel<<<Bsz, Hsz>>>(x, flg, flb, idxs, emb, logits);
}

// round 10
// speedup vs baseline: 1.1743x; 1.0009x over previous
#include <cuda_runtime.h>
#include <cstdint>

// Problem constants
#define Bsz 64
#define Lsz 200
#define Hsz 128
#define Ssz 64
#define Esz 256
#define NBsz 2
#define Kc  101
#define BLr (Bsz*Lsz)   // 12800 rows

// ---------------- scratch (device globals; no allocation allowed) -----------
__device__ float g_x   [BLr*Hsz];
__device__ float g_ln  [BLr*Hsz];
__device__ float g_xz  [BLr*2*Esz];
__device__ float g_xc  [BLr*Esz];
__device__ float g_xsum[BLr];
__device__ float g_ssm [BLr*3*Ssz];
__device__ float g_yc  [BLr];
__device__ float g_gate[BLr*Esz];

// ---------------- helpers ---------------------------------------------------
__device__ __forceinline__ float sigmoidf_(float x){ return 1.f/(1.f+__expf(-x)); }
__device__ __forceinline__ float siluf_(float x){ return x*sigmoidf_(x); }
__device__ __forceinline__ float softplusf_(float x){ return x>20.f ? x : log1pf(__expf(x)); }

template<int NW>
__device__ __forceinline__ float block_sum(float v, float* sm){
    #pragma unroll
    for (int o=16;o;o>>=1) v += __shfl_xor_sync(0xffffffffu, v, o);
    __syncthreads();
    if ((threadIdx.x&31)==0) sm[threadIdx.x>>5] = v;
    __syncthreads();
    float s = 0.f;
    #pragma unroll
    for (int i=0;i<NW;i++) s += sm[i];
    return s;
}

__device__ __forceinline__ float warp_sum(float v){
    #pragma unroll
    for (int o=16;o;o>>=1) v += __shfl_xor_sync(0xffffffffu, v, o);
    return v;
}

// mask-based tf32 split: hi keeps top 10 mantissa bits (tf32 HW reads 19 MSBs;
// lo has <=13 significant bits, HW truncation of lo costs ~2^-20 relative).
__device__ __forceinline__ float fhi_(float v){
    return __uint_as_float(__float_as_uint(v) & 0xffffe000u);
}
__device__ __forceinline__ float4 fhi4_(float4 v){
    return make_float4(fhi_(v.x), fhi_(v.y), fhi_(v.z), fhi_(v.w));
}
__device__ __forceinline__ float4 fsub4_(float4 a, float4 b){
    return make_float4(a.x-b.x, a.y-b.y, a.z-b.z, a.w-b.w);
}

__device__ __forceinline__ void mma16n8k8(float* c, const uint32_t* a, const uint32_t* b){
    asm volatile("mma.sync.aligned.m16n8k8.row.col.f32.tf32.tf32.f32 "
        "{%0,%1,%2,%3}, {%4,%5,%6,%7}, {%8,%9}, {%0,%1,%2,%3};"
        : "+f"(c[0]),"+f"(c[1]),"+f"(c[2]),"+f"(c[3])
        : "r"(a[0]),"r"(a[1]),"r"(a[2]),"r"(a[3]), "r"(b[0]),"r"(b[1]));
}

// ---------------- embed: x = (item_emb[seq] + pos) * mask, float4 ----------
__global__ void embed_kernel(const int* __restrict__ seqs, const float* __restrict__ emb,
                             const float* __restrict__ pos, float* __restrict__ x){
    int idx = blockIdx.x*blockDim.x + threadIdx.x;   // one thread = 4 floats
    if (idx >= BLr*(Hsz/4)) return;
    int h4 = (idx & 31) * 4;
    int bl = idx >> 5;
    int t  = bl % Lsz;
    int s  = seqs[bl];
    float4 o;
    if (s){
        float4 e = *(const float4*)(emb + (long)s*Hsz + h4);
        float4 p = *(const float4*)(pos + t*Hsz + h4);
        o = make_float4(e.x+p.x, e.y+p.y, e.z+p.z, e.w+p.w);
    } else {
        o = make_float4(0.f,0.f,0.f,0.f);
    }
    *(float4*)(x + (long)bl*Hsz + h4) = o;
}

// ---------------- layernorm H=128, warp-per-row -----------------------------
__global__ void ln128_kernel(const float* __restrict__ x, const float* __restrict__ g,
                             const float* __restrict__ b, float* __restrict__ out){
    int row  = blockIdx.x*4 + (threadIdx.x >> 5);
    int lane = threadIdx.x & 31;
    float4 v = *(const float4*)(x + (long)row*Hsz + lane*4);
    float m = warp_sum(v.x + v.y + v.z + v.w) * (1.f/Hsz);
    float4 d = make_float4(v.x-m, v.y-m, v.z-m, v.w-m);
    float var = warp_sum(d.x*d.x + d.y*d.y + d.z*d.z + d.w*d.w) * (1.f/Hsz);
    float inv = rsqrtf(var + 1e-5f);
    float4 gg = *(const float4*)(g + lane*4);
    float4 bb = *(const float4*)(b + lane*4);
    float4 o;
    o.x = d.x*inv*gg.x + bb.x;
    o.y = d.y*inv*gg.y + bb.y;
    o.z = d.z*inv*gg.z + bb.z;
    o.w = d.w*inv*gg.w + bb.w;
    *(float4*)(out + (long)row*Hsz + lane*4) = o;
}

// ---------------- 3xTF32 GEMM, hi/lo pre-split in SMEM ----------------------
// BM=128, BN=64, BK=16, 256 threads = 8 warps (4M x 2N), warp tile 32x32.
// If resid != nullptr: out = (resid + (A@W+b)) * (seqs[row]!=0)
#define GBM 128
#define GBN 64
#define GBK 16
#define ASTR 20   // bank = (20g+tg)%32 distinct for fragment reads
#define BSTR 72   // bank = (8tg+g)%32 distinct

__global__ __launch_bounds__(256) void gemm_tf32_kernel(
        const float* __restrict__ A, const float* __restrict__ W,
        const float* __restrict__ bias, float* __restrict__ C,
        int M, int Kd, int N,
        const float* __restrict__ resid, const int* __restrict__ mask_seq){
    __shared__ float Ah[GBM][ASTR], Al[GBM][ASTR];   // 2 x 10.0 KB
    __shared__ float Bh[GBK][BSTR], Bl[GBK][BSTR];   // 2 x 4.5 KB
    int tid  = threadIdx.x;
    int lane = tid & 31;
    int w    = tid >> 5;
    int warpM = w >> 1;
    int warpN = w & 1;
    int g  = lane >> 2;
    int tg = lane & 3;
    int bm = blockIdx.x * GBM;
    int bn = blockIdx.y * GBN;

    // global-load mapping (BK=16 tile)
    int arow = tid >> 2;             // 0..63 (plus +64)
    int acol = (tid & 3) * 4;        // 0,4,8,12
    int brow = tid >> 4;             // 0..15
    int bcol = (tid & 15) * 4;       // 0..60

    float acc[2][4][4];
    #pragma unroll
    for (int mi=0;mi<2;mi++)
        #pragma unroll
        for (int ni=0;ni<4;ni++)
            #pragma unroll
            for (int c=0;c<4;c++) acc[mi][ni][c]=0.f;

    // prefetch tile 0
    float4 pa[2], pb;
    pa[0] = *(const float4*)(A + (long)(bm + arow     )*Kd + acol);
    pa[1] = *(const float4*)(A + (long)(bm + arow + 64)*Kd + acol);
    pb    = *(const float4*)(W + (long)brow*N + bn + bcol);

    for (int kt = 0; kt < Kd; kt += GBK){
        // split + commit prefetched tile to SMEM
        #pragma unroll
        for (int r=0;r<2;r++){
            float4 h = fhi4_(pa[r]);
            float4 l = fsub4_(pa[r], h);
            *(float4*)&Ah[arow + 64*r][acol] = h;
            *(float4*)&Al[arow + 64*r][acol] = l;
        }
        {
            float4 h = fhi4_(pb);
            float4 l = fsub4_(pb, h);
            *(float4*)&Bh[brow][bcol] = h;
            *(float4*)&Bl[brow][bcol] = l;
        }
        __syncthreads();

        // prefetch next tile
        if (kt + GBK < Kd){
            pa[0] = *(const float4*)(A + (long)(bm + arow     )*Kd + kt + GBK + acol);
            pa[1] = *(const float4*)(A + (long)(bm + arow + 64)*Kd + kt + GBK + acol);
            pb    = *(const float4*)(W + (long)(kt + GBK + brow)*N + bn + bcol);
        }

        #pragma unroll
        for (int k8 = 0; k8 < GBK/8; k8++){
            int k0 = k8*8;
            uint32_t ah[2][4], al[2][4];
            #pragma unroll
            for (int mi=0;mi<2;mi++){
                int r0 = warpM*32 + mi*16 + g;
                ah[mi][0] = __float_as_uint(Ah[r0    ][k0 + tg    ]);
                ah[mi][1] = __float_as_uint(Ah[r0 + 8][k0 + tg    ]);
                ah[mi][2] = __float_as_uint(Ah[r0    ][k0 + tg + 4]);
                ah[mi][3] = __float_as_uint(Ah[r0 + 8][k0 + tg + 4]);
                al[mi][0] = __float_as_uint(Al[r0    ][k0 + tg    ]);
                al[mi][1] = __float_as_uint(Al[r0 + 8][k0 + tg    ]);
                al[mi][2] = __float_as_uint(Al[r0    ][k0 + tg + 4]);
                al[mi][3] = __float_as_uint(Al[r0 + 8][k0 + tg + 4]);
            }
            uint32_t bh[4][2], bl[4][2];
            #pragma unroll
            for (int ni=0;ni<4;ni++){
                int c0 = warpN*32 + ni*8 + g;
                bh[ni][0] = __float_as_uint(Bh[k0 + tg    ][c0]);
                bh[ni][1] = __float_as_uint(Bh[k0 + tg + 4][c0]);
                bl[ni][0] = __float_as_uint(Bl[k0 + tg    ][c0]);
                bl[ni][1] = __float_as_uint(Bl[k0 + tg + 4][c0]);
            }
            #pragma unroll
            for (int mi=0;mi<2;mi++)
                #pragma unroll
                for (int ni=0;ni<4;ni++){
                    mma16n8k8(acc[mi][ni], ah[mi], bh[ni]);
                    mma16n8k8(acc[mi][ni], ah[mi], bl[ni]);
                    mma16n8k8(acc[mi][ni], al[mi], bh[ni]);
                }
        }
        __syncthreads();
    }

    // epilogue
    #pragma unroll
    for (int mi=0;mi<2;mi++){
        int r0 = bm + warpM*32 + mi*16 + g;
        #pragma unroll
        for (int ni=0;ni<4;ni++){
            int col = bn + warpN*32 + ni*8 + 2*tg;
            float b0 = bias[col], b1 = bias[col+1];
            float v00 = acc[mi][ni][0] + b0, v01 = acc[mi][ni][1] + b1;
            float v10 = acc[mi][ni][2] + b0, v11 = acc[mi][ni][3] + b1;
            if (resid){
                float m0 = (mask_seq[r0]   != 0) ? 1.f : 0.f;
                float m1 = (mask_seq[r0+8] != 0) ? 1.f : 0.f;
                const float* rr0 = resid + (long)r0*N + col;
                const float* rr1 = resid + (long)(r0+8)*N + col;
                v00 = (rr0[0] + v00)*m0; v01 = (rr0[1] + v01)*m0;
                v10 = (rr1[0] + v10)*m1; v11 = (rr1[1] + v11)*m1;
            }
            *(float2*)(C + (long)r0*N + col)     = make_float2(v00, v01);
            *(float2*)(C + (long)(r0+8)*N + col) = make_float2(v10, v11);
        }
    }
}

// ---------------- depthwise conv(k=3,pad=1)+silu+row-sum, warp-per-row ------
__global__ void conv_kernel(const float* __restrict__ xz, const float* __restrict__ cw,
                            const float* __restrict__ cb, float* __restrict__ xc,
                            float* __restrict__ xsum){
    int row  = blockIdx.x*4 + (threadIdx.x >> 5);
    int lane = threadIdx.x & 31;
    int t = row % Lsz;
    int e0 = lane*8;
    const float* rp = xz + (long)row*(2*Esz) + e0;
    float4 c0a = *(const float4*)(rp);
    float4 c0b = *(const float4*)(rp + 4);
    float4 cma, cmb, cpa, cpb;
    if (t > 0){ cma = *(const float4*)(rp - 2*Esz); cmb = *(const float4*)(rp - 2*Esz + 4); }
    else      { cma = make_float4(0.f,0.f,0.f,0.f); cmb = cma; }
    if (t < Lsz-1){ cpa = *(const float4*)(rp + 2*Esz); cpb = *(const float4*)(rp + 2*Esz + 4); }
    else          { cpa = make_float4(0.f,0.f,0.f,0.f); cpb = cpa; }
    // vectorized weight/bias loads: 24 cw floats (96B aligned), 8 cb floats
    float wreg[24];
    #pragma unroll
    for (int i=0;i<6;i++)
        *(float4*)(wreg + i*4) = *(const float4*)(cw + e0*3 + i*4);
    float breg[8];
    *(float4*)(breg)     = *(const float4*)(cb + e0);
    *(float4*)(breg + 4) = *(const float4*)(cb + e0 + 4);

    float xm[8] = {cma.x,cma.y,cma.z,cma.w, cmb.x,cmb.y,cmb.z,cmb.w};
    float x0[8] = {c0a.x,c0a.y,c0a.z,c0a.w, c0b.x,c0b.y,c0b.z,c0b.w};
    float xp[8] = {cpa.x,cpa.y,cpa.z,cpa.w, cpb.x,cpb.y,cpb.z,cpb.w};
    float s[8];
    float tot = 0.f;
    #pragma unroll
    for (int i=0;i<8;i++){
        float v = fmaf(xm[i], wreg[i*3+0], fmaf(x0[i], wreg[i*3+1], fmaf(xp[i], wreg[i*3+2], breg[i])));
        s[i] = siluf_(v);
        tot += s[i];
    }
    tot = warp_sum(tot);
    if (lane == 0) xsum[row] = tot;
    float* op = xc + (long)row*Esz + e0;
    *(float4*)(op)     = make_float4(s[0],s[1],s[2],s[3]);
    *(float4*)(op + 4) = make_float4(s[4],s[5],s[6],s[7]);
}

// ---------------- sequential SSM scan (state collapsed to [B,S]) ------------
__global__ __launch_bounds__(256) void scan_kernel(
        const float* __restrict__ ssm, const float* __restrict__ xsum,
        const float* __restrict__ A_log, float* __restrict__ yc){
    __shared__ float A_s[Ssz], h_s[Ssz], dB_s[Ssz], C_s[Ssz], delta_s[Ssz], prod_s[Ssz];
    __shared__ float xs_sh;
    int b = blockIdx.x;
    int tid = threadIdx.x;          // 256
    int i = tid >> 2;
    int q = tid & 3;

    if (tid < Ssz){
        A_s[tid] = -__expf(fminf(fmaxf(A_log[tid], -5.f), 5.f));
        h_s[tid] = 0.f;
    }
    __syncthreads();
    float Areg[16];
    #pragma unroll
    for (int jj=0;jj<16;jj++) Areg[jj] = A_s[q*16+jj];

    const float* srow = ssm + (long)b*Lsz*(3*Ssz);
    float nd=0.f, nb=0.f, nc=0.f, nxs=0.f;
    if (tid < Ssz){ nd = srow[tid]; nb = srow[Ssz+tid]; nc = srow[2*Ssz+tid]; }
    if (tid == 0) nxs = xsum[b*Lsz];

    for (int t=0; t<Lsz; t++){
        if (tid < Ssz){
            float d = softplusf_(nd);
            delta_s[tid] = d;
            dB_s[tid] = d * nb;
            C_s[tid]  = nc;
        }
        if (tid == 0) xs_sh = nxs;
        __syncthreads();
        if (t+1 < Lsz){
            const float* nr = srow + (long)(t+1)*(3*Ssz);
            if (tid < Ssz){ nd = nr[tid]; nb = nr[Ssz+tid]; nc = nr[2*Ssz+tid]; }
            if (tid == 0) nxs = xsum[b*Lsz + t + 1];
        }
        float di = delta_s[i];
        float partial = 0.f;
        #pragma unroll
        for (int jj=0;jj<16;jj++){
            int j = q*16 + jj;
            float w = __expf(fmaxf(di * Areg[jj], -10.f));
            partial = fmaf(w, h_s[j], partial);
        }
        partial += __shfl_xor_sync(0xffffffffu, partial, 1);
        partial += __shfl_xor_sync(0xffffffffu, partial, 2);
        float hn = 0.f, pr = 0.f;
        if (q == 0){
            hn = partial + dB_s[i]*xs_sh;
            hn = fminf(fmaxf(hn, -100.f), 100.f);
            pr = hn * C_s[i];
        }
        __syncthreads();
        if (q == 0){ h_s[i] = hn; prod_s[i] = pr; }
        __syncthreads();
        if (tid < 32){
            float v = prod_s[tid] + prod_s[tid+32];
            #pragma unroll
            for (int o=16;o;o>>=1) v += __shfl_xor_sync(0xffffffffu, v, o);
            if (tid == 0) yc[b*Lsz + t] = v;
        }
    }
}

// ---------------- y = LN_E(yc + D*xc) * silu(z), warp-per-row ---------------
__global__ void gate_kernel(const float* __restrict__ xc, const float* __restrict__ yc,
                            const float* __restrict__ xz, const float* __restrict__ Dp,
                            const float* __restrict__ ig, const float* __restrict__ ib,
                            float* __restrict__ out){
    int row  = blockIdx.x*4 + (threadIdx.x >> 5);
    int lane = threadIdx.x & 31;
    float ycr = yc[row];
    float4 a0 = *(const float4*)(xc + (long)row*Esz + lane*8);
    float4 a1 = *(const float4*)(xc + (long)row*Esz + lane*8 + 4);
    float4 d0 = *(const float4*)(Dp + lane*8);
    float4 d1 = *(const float4*)(Dp + lane*8 + 4);
    float v[8];
    v[0]=ycr+d0.x*a0.x; v[1]=ycr+d0.y*a0.y; v[2]=ycr+d0.z*a0.z; v[3]=ycr+d0.w*a0.w;
    v[4]=ycr+d1.x*a1.x; v[5]=ycr+d1.y*a1.y; v[6]=ycr+d1.z*a1.z; v[7]=ycr+d1.w*a1.w;
    float s = 0.f;
    #pragma unroll
    for (int i=0;i<8;i++) s += v[i];
    float m = warp_sum(s) * (1.f/Esz);
    float vs = 0.f;
    #pragma unroll
    for (int i=0;i<8;i++){ v[i] -= m; vs += v[i]*v[i]; }
    float var = warp_sum(vs) * (1.f/Esz);
    float inv = rsqrtf(var + 1e-5f);
    float4 g0 = *(const float4*)(ig + lane*8);
    float4 g1 = *(const float4*)(ig + lane*8 + 4);
    float4 b0 = *(const float4*)(ib + lane*8);
    float4 b1 = *(const float4*)(ib + lane*8 + 4);
    float4 z0 = *(const float4*)(xz + (long)row*(2*Esz) + Esz + lane*8);
    float4 z1 = *(const float4*)(xz + (long)row*(2*Esz) + Esz + lane*8 + 4);
    float4 o0, o1;
    o0.x = (v[0]*inv*g0.x + b0.x) * siluf_(z0.x);
    o0.y = (v[1]*inv*g0.y + b0.y) * siluf_(z0.y);
    o0.z = (v[2]*inv*g0.z + b0.z) * siluf_(z0.z);
    o0.w = (v[3]*inv*g0.w + b0.w) * siluf_(z0.w);
    o1.x = (v[4]*inv*g1.x + b1.x) * siluf_(z1.x);
    o1.y = (v[5]*inv*g1.y + b1.y) * siluf_(z1.y);
    o1.z = (v[6]*inv*g1.z + b1.z) * siluf_(z1.z);
    o1.w = (v[7]*inv*g1.w + b1.w) * siluf_(z1.w);
    *(float4*)(out + (long)row*Esz + lane*8)     = o0;
    *(float4*)(out + (long)row*Esz + lane*8 + 4) = o1;
}

// ---------------- final LN (last step only) + candidate logits --------------
__global__ void final_kernel(const float* __restrict__ x, const float* __restrict__ fg,
                             const float* __restrict__ fb, const int* __restrict__ idxs,
                             const float* __restrict__ emb, float* __restrict__ out){
    __shared__ float sm[4];
    __shared__ float xf[Hsz];
    int b = blockIdx.x;
    int tid = threadIdx.x;  // 128
    const float* xr = x + (long)(b*Lsz + Lsz-1)*Hsz;
    float v = xr[tid];
    float m = block_sum<4>(v, sm) * (1.f/Hsz);
    float d = v - m;
    float var = block_sum<4>(d*d, sm) * (1.f/Hsz);
    float inv = rsqrtf(var + 1e-5f);
    xf[tid] = d*inv*fg[tid] + fb[tid];
    __syncthreads();
    int w = tid >> 5, l = tid & 31;
    for (int k = w; k < Kc; k += 4){
        int idx = idxs[b*Kc + k];
        const float* er = emb + (long)idx*Hsz;
        float acc = 0.f;
        #pragma unroll
        for (int r=0;r<4;r++) acc = fmaf(xf[l+32*r], er[l+32*r], acc);
        #pragma unroll
        for (int o=16;o;o>>=1) acc += __shfl_xor_sync(0xffffffffu, acc, o);
        if (l == 0) out[b*Kc + k] = acc;
    }
}

// ---------------- host orchestration ----------------------------------------
extern "C" void kernel_launch(void* const* d_in, const int* in_sizes, int n_in,
                              void* d_out, int out_size){
    const int*   seqs  = (const int*)  d_in[0];
    const int*   idxs  = (const int*)  d_in[1];
    const float* emb   = (const float*)d_in[2];
    const float* pos   = (const float*)d_in[3];
    const float* blkg  = (const float*)d_in[4];
    const float* blkb  = (const float*)d_in[5];
    const float* in_w  = (const float*)d_in[6];
    const float* in_b  = (const float*)d_in[7];
    const float* convw = (const float*)d_in[8];
    const float* convb = (const float*)d_in[9];
    const float* xp_w  = (const float*)d_in[10];
    const float* xp_b  = (const float*)d_in[11];
    const float* A_log = (const float*)d_in[12];
    const float* Dp    = (const float*)d_in[13];
    const float* out_w = (const float*)d_in[14];
    const float* out_b = (const float*)d_in[15];
    const float* ilg   = (const float*)d_in[16];
    const float* ilb   = (const float*)d_in[17];
    const float* flg   = (const float*)d_in[18];
    const float* flb   = (const float*)d_in[19];
    float* logits = (float*)d_out;

    float *x,*ln,*xz,*xc,*xs,*ssm,*yc,*gate;
    cudaGetSymbolAddress((void**)&x,    g_x);
    cudaGetSymbolAddress((void**)&ln,   g_ln);
    cudaGetSymbolAddress((void**)&xz,   g_xz);
    cudaGetSymbolAddress((void**)&xc,   g_xc);
    cudaGetSymbolAddress((void**)&xs,   g_xsum);
    cudaGetSymbolAddress((void**)&ssm,  g_ssm);
    cudaGetSymbolAddress((void**)&yc,   g_yc);
    cudaGetSymbolAddress((void**)&gate, g_gate);

    embed_kernel<<<(BLr*(Hsz/4) + 255)/256, 256>>>(seqs, emb, pos, x);

    for (int blk = 0; blk < NBsz; blk++){
        ln128_kernel<<<BLr/4, 128>>>(x, blkg + blk*Hsz, blkb + blk*Hsz, ln);

        gemm_tf32_kernel<<<dim3(BLr/GBM, (2*Esz)/GBN), 256>>>(
            ln, in_w + (long)blk*Hsz*2*Esz, in_b + blk*2*Esz, xz,
            BLr, Hsz, 2*Esz, nullptr, nullptr);

        conv_kernel<<<BLr/4, 128>>>(xz, convw + blk*Esz*3, convb + blk*Esz, xc, xs);

        gemm_tf32_kernel<<<dim3(BLr/GBM, (3*Ssz)/GBN), 256>>>(
            xc, xp_w + (long)blk*Esz*3*Ssz, xp_b + blk*3*Ssz, ssm,
            BLr, Esz, 3*Ssz, nullptr, nullptr);

        scan_kernel<<<Bsz, 256>>>(ssm, xs, A_log + blk*Ssz, yc);

        gate_kernel<<<BLr/4, 128>>>(xc, yc, xz, Dp + blk*Esz, ilg + blk*Esz, ilb + blk*Esz, gate);

        gemm_tf32_kernel<<<dim3(BLr/GBM, Hsz/GBN), 256>>>(
            gate, out_w + (long)blk*Esz*Hsz, out_b + blk*Hsz, x,
            BLr, Esz, Hsz, x, seqs);
    }

    final_kernel<<<Bsz, Hsz>>>(x, flg, flb, idxs, emb, logits);
}

// round 11
// speedup vs baseline: 1.3450x; 1.1454x over previous
#include <cuda_runtime.h>
#include <cuda_bf16.h>
#include <cstdint>

// Problem constants
#define Bsz 64
#define Lsz 200
#define Hsz 128
#define Ssz 64
#define Esz 256
#define NBsz 2
#define Kc  101
#define BLr (Bsz*Lsz)   // 12800 rows

// ---------------- scratch (device globals; no allocation allowed) -----------
__device__ float g_x   [BLr*Hsz];
__device__ float g_ln  [BLr*Hsz];
__device__ float g_xz  [BLr*2*Esz];
__device__ float g_xc  [BLr*Esz];
__device__ float g_xsum[BLr];
__device__ float g_ssm [BLr*3*Ssz];
__device__ float g_yc  [BLr];
__device__ float g_gate[BLr*Esz];

// ---------------- helpers ---------------------------------------------------
__device__ __forceinline__ float sigmoidf_(float x){ return 1.f/(1.f+__expf(-x)); }
__device__ __forceinline__ float siluf_(float x){ return x*sigmoidf_(x); }
__device__ __forceinline__ float softplusf_(float x){ return x>20.f ? x : log1pf(__expf(x)); }

template<int NW>
__device__ __forceinline__ float block_sum(float v, float* sm){
    #pragma unroll
    for (int o=16;o;o>>=1) v += __shfl_xor_sync(0xffffffffu, v, o);
    __syncthreads();
    if ((threadIdx.x&31)==0) sm[threadIdx.x>>5] = v;
    __syncthreads();
    float s = 0.f;
    #pragma unroll
    for (int i=0;i<NW;i++) s += sm[i];
    return s;
}

__device__ __forceinline__ float warp_sum(float v){
    #pragma unroll
    for (int o=16;o;o>>=1) v += __shfl_xor_sync(0xffffffffu, v, o);
    return v;
}

// pack two fp32 (consecutive K) into bf16x2 hi + bf16x2 lo words
__device__ __forceinline__ void packbf(float2 v, uint32_t& hi, uint32_t& lo){
    __nv_bfloat162 h2 = __float22bfloat162_rn(v);
    float2 hf = __bfloat1622float2(h2);
    __nv_bfloat162 l2 = __float22bfloat162_rn(make_float2(v.x-hf.x, v.y-hf.y));
    hi = *reinterpret_cast<uint32_t*>(&h2);
    lo = *reinterpret_cast<uint32_t*>(&l2);
}

__device__ __forceinline__ void mma16n8k16bf(float* c, const uint32_t* a, const uint32_t* b){
    asm volatile("mma.sync.aligned.m16n8k16.row.col.f32.bf16.bf16.f32 "
        "{%0,%1,%2,%3}, {%4,%5,%6,%7}, {%8,%9}, {%0,%1,%2,%3};"
        : "+f"(c[0]),"+f"(c[1]),"+f"(c[2]),"+f"(c[3])
        : "r"(a[0]),"r"(a[1]),"r"(a[2]),"r"(a[3]), "r"(b[0]),"r"(b[1]));
}

// ---------------- embed: x = (item_emb[seq] + pos) * mask, float4 ----------
__global__ void embed_kernel(const int* __restrict__ seqs, const float* __restrict__ emb,
                             const float* __restrict__ pos, float* __restrict__ x){
    int idx = blockIdx.x*blockDim.x + threadIdx.x;
    if (idx >= BLr*(Hsz/4)) return;
    int h4 = (idx & 31) * 4;
    int bl = idx >> 5;
    int t  = bl % Lsz;
    int s  = seqs[bl];
    float4 o;
    if (s){
        float4 e = *(const float4*)(emb + (long)s*Hsz + h4);
        float4 p = *(const float4*)(pos + t*Hsz + h4);
        o = make_float4(e.x+p.x, e.y+p.y, e.z+p.z, e.w+p.w);
    } else {
        o = make_float4(0.f,0.f,0.f,0.f);
    }
    *(float4*)(x + (long)bl*Hsz + h4) = o;
}

// ---------------- layernorm H=128, warp-per-row -----------------------------
__global__ void ln128_kernel(const float* __restrict__ x, const float* __restrict__ g,
                             const float* __restrict__ b, float* __restrict__ out){
    int row  = blockIdx.x*4 + (threadIdx.x >> 5);
    int lane = threadIdx.x & 31;
    float4 v = *(const float4*)(x + (long)row*Hsz + lane*4);
    float m = warp_sum(v.x + v.y + v.z + v.w) * (1.f/Hsz);
    float4 d = make_float4(v.x-m, v.y-m, v.z-m, v.w-m);
    float var = warp_sum(d.x*d.x + d.y*d.y + d.z*d.z + d.w*d.w) * (1.f/Hsz);
    float inv = rsqrtf(var + 1e-5f);
    float4 gg = *(const float4*)(g + lane*4);
    float4 bb = *(const float4*)(b + lane*4);
    float4 o;
    o.x = d.x*inv*gg.x + bb.x;
    o.y = d.y*inv*gg.y + bb.y;
    o.z = d.z*inv*gg.z + bb.z;
    o.w = d.w*inv*gg.w + bb.w;
    *(float4*)(out + (long)row*Hsz + lane*4) = o;
}

// ---------------- bf16 hi/lo GEMM (3x m16n8k16): C = A@W + bias -------------
// BM=128, BN=64, BK=32, 256 threads = 8 warps (4M x 2N), warp tile 32x32.
// A,B stored packed bf16x2-along-K, hi and lo planes.
// If resid != nullptr: out = (resid + (A@W+b)) * (seqs[row]!=0)
#define GBM 128
#define GBN 64
#define GBK 32
#define AWRD (GBK/2)    // 16 words per A row
#define ASTR 20         // A word stride: bank = (20g+tg)%32 distinct
#define BSTR 72         // B word stride: bank = (8p+g)%32 distinct

__global__ __launch_bounds__(256) void gemm_tf32_kernel(
        const float* __restrict__ A, const float* __restrict__ W,
        const float* __restrict__ bias, float* __restrict__ C,
        int M, int Kd, int N,
        const float* __restrict__ resid, const int* __restrict__ mask_seq){
    __shared__ uint32_t Ah[GBM][ASTR], Al[GBM][ASTR];   // 2 x 10.0 KB
    __shared__ uint32_t Bh[GBK/2][BSTR], Bl[GBK/2][BSTR]; // 2 x 4.5 KB
    int tid  = threadIdx.x;
    int lane = tid & 31;
    int w    = tid >> 5;
    int warpM = w >> 1;
    int warpN = w & 1;
    int g  = lane >> 2;
    int tg = lane & 3;
    int bm = blockIdx.x * GBM;
    int bn = blockIdx.y * GBN;

    // global-load mapping
    int arow = tid >> 3;             // 0..31 (+32r)
    int acol = (tid & 7) * 4;        // K offset 0..28
    int awc  = (tid & 7) * 2;        // word col 0..14
    int bp   = tid >> 4;             // k-pair 0..15
    int bcol = (tid & 15) * 4;       // n offset 0..60

    float acc[2][4][4];
    #pragma unroll
    for (int mi=0;mi<2;mi++)
        #pragma unroll
        for (int ni=0;ni<4;ni++)
            #pragma unroll
            for (int c=0;c<4;c++) acc[mi][ni][c]=0.f;

    // prefetch tile 0
    float4 pa[4], pb0, pb1;
    #pragma unroll
    for (int r=0;r<4;r++)
        pa[r] = *(const float4*)(A + (long)(bm + arow + 32*r)*Kd + acol);
    pb0 = *(const float4*)(W + (long)(2*bp    )*N + bn + bcol);
    pb1 = *(const float4*)(W + (long)(2*bp + 1)*N + bn + bcol);

    for (int kt = 0; kt < Kd; kt += GBK){
        // pack + commit prefetched tile to SMEM
        #pragma unroll
        for (int r=0;r<4;r++){
            uint32_t h0,l0,h1,l1;
            packbf(make_float2(pa[r].x, pa[r].y), h0, l0);
            packbf(make_float2(pa[r].z, pa[r].w), h1, l1);
            Ah[arow+32*r][awc]   = h0;  Ah[arow+32*r][awc+1] = h1;
            Al[arow+32*r][awc]   = l0;  Al[arow+32*r][awc+1] = l1;
        }
        {
            uint32_t hw[4], lw[4];
            packbf(make_float2(pb0.x, pb1.x), hw[0], lw[0]);
            packbf(make_float2(pb0.y, pb1.y), hw[1], lw[1]);
            packbf(make_float2(pb0.z, pb1.z), hw[2], lw[2]);
            packbf(make_float2(pb0.w, pb1.w), hw[3], lw[3]);
            #pragma unroll
            for (int j=0;j<4;j++){ Bh[bp][bcol+j] = hw[j]; Bl[bp][bcol+j] = lw[j]; }
        }
        __syncthreads();

        // prefetch next tile
        if (kt + GBK < Kd){
            #pragma unroll
            for (int r=0;r<4;r++)
                pa[r] = *(const float4*)(A + (long)(bm + arow + 32*r)*Kd + kt + GBK + acol);
            pb0 = *(const float4*)(W + (long)(kt + GBK + 2*bp    )*N + bn + bcol);
            pb1 = *(const float4*)(W + (long)(kt + GBK + 2*bp + 1)*N + bn + bcol);
        }

        #pragma unroll
        for (int k16 = 0; k16 < GBK/16; k16++){
            int w0 = k16*8;   // word base of this K16 chunk
            uint32_t ah[2][4], al[2][4];
            #pragma unroll
            for (int mi=0;mi<2;mi++){
                int r0 = warpM*32 + mi*16 + g;
                ah[mi][0] = Ah[r0    ][w0 + tg    ];
                ah[mi][1] = Ah[r0 + 8][w0 + tg    ];
                ah[mi][2] = Ah[r0    ][w0 + tg + 4];
                ah[mi][3] = Ah[r0 + 8][w0 + tg + 4];
                al[mi][0] = Al[r0    ][w0 + tg    ];
                al[mi][1] = Al[r0 + 8][w0 + tg    ];
                al[mi][2] = Al[r0    ][w0 + tg + 4];
                al[mi][3] = Al[r0 + 8][w0 + tg + 4];
            }
            uint32_t bh[4][2], bl[4][2];
            #pragma unroll
            for (int ni=0;ni<4;ni++){
                int c0 = warpN*32 + ni*8 + g;
                bh[ni][0] = Bh[w0 + tg    ][c0];
                bh[ni][1] = Bh[w0 + tg + 4][c0];
                bl[ni][0] = Bl[w0 + tg    ][c0];
                bl[ni][1] = Bl[w0 + tg + 4][c0];
            }
            #pragma unroll
            for (int mi=0;mi<2;mi++)
                #pragma unroll
                for (int ni=0;ni<4;ni++){
                    mma16n8k16bf(acc[mi][ni], ah[mi], bh[ni]);
                    mma16n8k16bf(acc[mi][ni], ah[mi], bl[ni]);
                    mma16n8k16bf(acc[mi][ni], al[mi], bh[ni]);
                }
        }
        __syncthreads();
    }

    // epilogue (same C mapping as m16n8k8)
    #pragma unroll
    for (int mi=0;mi<2;mi++){
        int r0 = bm + warpM*32 + mi*16 + g;
        #pragma unroll
        for (int ni=0;ni<4;ni++){
            int col = bn + warpN*32 + ni*8 + 2*tg;
            float b0 = bias[col], b1 = bias[col+1];
            float v00 = acc[mi][ni][0] + b0, v01 = acc[mi][ni][1] + b1;
            float v10 = acc[mi][ni][2] + b0, v11 = acc[mi][ni][3] + b1;
            if (resid){
                float m0 = (mask_seq[r0]   != 0) ? 1.f : 0.f;
                float m1 = (mask_seq[r0+8] != 0) ? 1.f : 0.f;
                const float* rr0 = resid + (long)r0*N + col;
                const float* rr1 = resid + (long)(r0+8)*N + col;
                v00 = (rr0[0] + v00)*m0; v01 = (rr0[1] + v01)*m0;
                v10 = (rr1[0] + v10)*m1; v11 = (rr1[1] + v11)*m1;
            }
            *(float2*)(C + (long)r0*N + col)     = make_float2(v00, v01);
            *(float2*)(C + (long)(r0+8)*N + col) = make_float2(v10, v11);
        }
    }
}

// ---------------- depthwise conv(k=3,pad=1)+silu+row-sum, warp-per-row ------
__global__ void conv_kernel(const float* __restrict__ xz, const float* __restrict__ cw,
                            const float* __restrict__ cb, float* __restrict__ xc,
                            float* __restrict__ xsum){
    int row  = blockIdx.x*4 + (threadIdx.x >> 5);
    int lane = threadIdx.x & 31;
    int t = row % Lsz;
    int e0 = lane*8;
    const float* rp = xz + (long)row*(2*Esz) + e0;
    float4 c0a = *(const float4*)(rp);
    float4 c0b = *(const float4*)(rp + 4);
    float4 cma, cmb, cpa, cpb;
    if (t > 0){ cma = *(const float4*)(rp - 2*Esz); cmb = *(const float4*)(rp - 2*Esz + 4); }
    else      { cma = make_float4(0.f,0.f,0.f,0.f); cmb = cma; }
    if (t < Lsz-1){ cpa = *(const float4*)(rp + 2*Esz); cpb = *(const float4*)(rp + 2*Esz + 4); }
    else          { cpa = make_float4(0.f,0.f,0.f,0.f); cpb = cpa; }
    float wreg[24];
    #pragma unroll
    for (int i=0;i<6;i++)
        *(float4*)(wreg + i*4) = *(const float4*)(cw + e0*3 + i*4);
    float breg[8];
    *(float4*)(breg)     = *(const float4*)(cb + e0);
    *(float4*)(breg + 4) = *(const float4*)(cb + e0 + 4);

    float xm[8] = {cma.x,cma.y,cma.z,cma.w, cmb.x,cmb.y,cmb.z,cmb.w};
    float x0[8] = {c0a.x,c0a.y,c0a.z,c0a.w, c0b.x,c0b.y,c0b.z,c0b.w};
    float xp[8] = {cpa.x,cpa.y,cpa.z,cpa.w, cpb.x,cpb.y,cpb.z,cpb.w};
    float s[8];
    float tot = 0.f;
    #pragma unroll
    for (int i=0;i<8;i++){
        float v = fmaf(xm[i], wreg[i*3+0], fmaf(x0[i], wreg[i*3+1], fmaf(xp[i], wreg[i*3+2], breg[i])));
        s[i] = siluf_(v);
        tot += s[i];
    }
    tot = warp_sum(tot);
    if (lane == 0) xsum[row] = tot;
    float* op = xc + (long)row*Esz + e0;
    *(float4*)(op)     = make_float4(s[0],s[1],s[2],s[3]);
    *(float4*)(op + 4) = make_float4(s[4],s[5],s[6],s[7]);
}

// ---------------- sequential SSM scan (state collapsed to [B,S]) ------------
__global__ __launch_bounds__(256) void scan_kernel(
        const float* __restrict__ ssm, const float* __restrict__ xsum,
        const float* __restrict__ A_log, float* __restrict__ yc){
    __shared__ float A_s[Ssz], h_s[Ssz], dB_s[Ssz], C_s[Ssz], delta_s[Ssz], prod_s[Ssz];
    __shared__ float xs_sh;
    int b = blockIdx.x;
    int tid = threadIdx.x;          // 256
    int i = tid >> 2;
    int q = tid & 3;

    if (tid < Ssz){
        A_s[tid] = -__expf(fminf(fmaxf(A_log[tid], -5.f), 5.f));
        h_s[tid] = 0.f;
    }
    __syncthreads();
    float Areg[16];
    #pragma unroll
    for (int jj=0;jj<16;jj++) Areg[jj] = A_s[q*16+jj];

    const float* srow = ssm + (long)b*Lsz*(3*Ssz);
    float nd=0.f, nb=0.f, nc=0.f, nxs=0.f;
    if (tid < Ssz){ nd = srow[tid]; nb = srow[Ssz+tid]; nc = srow[2*Ssz+tid]; }
    if (tid == 0) nxs = xsum[b*Lsz];

    for (int t=0; t<Lsz; t++){
        if (tid < Ssz){
            float d = softplusf_(nd);
            delta_s[tid] = d;
            dB_s[tid] = d * nb;
            C_s[tid]  = nc;
        }
        if (tid == 0) xs_sh = nxs;
        __syncthreads();
        if (t+1 < Lsz){
            const float* nr = srow + (long)(t+1)*(3*Ssz);
            if (tid < Ssz){ nd = nr[tid]; nb = nr[Ssz+tid]; nc = nr[2*Ssz+tid]; }
            if (tid == 0) nxs = xsum[b*Lsz + t + 1];
        }
        float di = delta_s[i];
        float partial = 0.f;
        #pragma unroll
        for (int jj=0;jj<16;jj++){
            int j = q*16 + jj;
            float w = __expf(fmaxf(di * Areg[jj], -10.f));
            partial = fmaf(w, h_s[j], partial);
        }
        partial += __shfl_xor_sync(0xffffffffu, partial, 1);
        partial += __shfl_xor_sync(0xffffffffu, partial, 2);
        float hn = 0.f, pr = 0.f;
        if (q == 0){
            hn = partial + dB_s[i]*xs_sh;
            hn = fminf(fmaxf(hn, -100.f), 100.f);
            pr = hn * C_s[i];
        }
        __syncthreads();
        if (q == 0){ h_s[i] = hn; prod_s[i] = pr; }
        __syncthreads();
        if (tid < 32){
            float v = prod_s[tid] + prod_s[tid+32];
            #pragma unroll
            for (int o=16;o;o>>=1) v += __shfl_xor_sync(0xffffffffu, v, o);
            if (tid == 0) yc[b*Lsz + t] = v;
        }
    }
}

// ---------------- y = LN_E(yc + D*xc) * silu(z), warp-per-row ---------------
__global__ void gate_kernel(const float* __restrict__ xc, const float* __restrict__ yc,
                            const float* __restrict__ xz, const float* __restrict__ Dp,
                            const float* __restrict__ ig, const float* __restrict__ ib,
                            float* __restrict__ out){
    int row  = blockIdx.x*4 + (threadIdx.x >> 5);
    int lane = threadIdx.x & 31;
    float ycr = yc[row];
    float4 a0 = *(const float4*)(xc + (long)row*Esz + lane*8);
    float4 a1 = *(const float4*)(xc + (long)row*Esz + lane*8 + 4);
    float4 d0 = *(const float4*)(Dp + lane*8);
    float4 d1 = *(const float4*)(Dp + lane*8 + 4);
    float v[8];
    v[0]=ycr+d0.x*a0.x; v[1]=ycr+d0.y*a0.y; v[2]=ycr+d0.z*a0.z; v[3]=ycr+d0.w*a0.w;
    v[4]=ycr+d1.x*a1.x; v[5]=ycr+d1.y*a1.y; v[6]=ycr+d1.z*a1.z; v[7]=ycr+d1.w*a1.w;
    float s = 0.f;
    #pragma unroll
    for (int i=0;i<8;i++) s += v[i];
    float m = warp_sum(s) * (1.f/Esz);
    float vs = 0.f;
    #pragma unroll
    for (int i=0;i<8;i++){ v[i] -= m; vs += v[i]*v[i]; }
    float var = warp_sum(vs) * (1.f/Esz);
    float inv = rsqrtf(var + 1e-5f);
    float4 g0 = *(const float4*)(ig + lane*8);
    float4 g1 = *(const float4*)(ig + lane*8 + 4);
    float4 b0 = *(const float4*)(ib + lane*8);
    float4 b1 = *(const float4*)(ib + lane*8 + 4);
    float4 z0 = *(const float4*)(xz + (long)row*(2*Esz) + Esz + lane*8);
    float4 z1 = *(const float4*)(xz + (long)row*(2*Esz) + Esz + lane*8 + 4);
    float4 o0, o1;
    o0.x = (v[0]*inv*g0.x + b0.x) * siluf_(z0.x);
    o0.y = (v[1]*inv*g0.y + b0.y) * siluf_(z0.y);
    o0.z = (v[2]*inv*g0.z + b0.z) * siluf_(z0.z);
    o0.w = (v[3]*inv*g0.w + b0.w) * siluf_(z0.w);
    o1.x = (v[4]*inv*g1.x + b1.x) * siluf_(z1.x);
    o1.y = (v[5]*inv*g1.y + b1.y) * siluf_(z1.y);
    o1.z = (v[6]*inv*g1.z + b1.z) * siluf_(z1.z);
    o1.w = (v[7]*inv*g1.w + b1.w) * siluf_(z1.w);
    *(float4*)(out + (long)row*Esz + lane*8)     = o0;
    *(float4*)(out + (long)row*Esz + lane*8 + 4) = o1;
}

// ---------------- final LN (last step only) + candidate logits --------------
__global__ void final_kernel(const float* __restrict__ x, const float* __restrict__ fg,
                             const float* __restrict__ fb, const int* __restrict__ idxs,
                             const float* __restrict__ emb, float* __restrict__ out){
    __shared__ float sm[4];
    __shared__ float xf[Hsz];
    int b = blockIdx.x;
    int tid = threadIdx.x;  // 128
    const float* xr = x + (long)(b*Lsz + Lsz-1)*Hsz;
    float v = xr[tid];
    float m = block_sum<4>(v, sm) * (1.f/Hsz);
    float d = v - m;
    float var = block_sum<4>(d*d, sm) * (1.f/Hsz);
    float inv = rsqrtf(var + 1e-5f);
    xf[tid] = d*inv*fg[tid] + fb[tid];
    __syncthreads();
    int w = tid >> 5, l = tid & 31;
    for (int k = w; k < Kc; k += 4){
        int idx = idxs[b*Kc + k];
        const float* er = emb + (long)idx*Hsz;
        float acc = 0.f;
        #pragma unroll
        for (int r=0;r<4;r++) acc = fmaf(xf[l+32*r], er[l+32*r], acc);
        #pragma unroll
        for (int o=16;o;o>>=1) acc += __shfl_xor_sync(0xffffffffu, acc, o);
        if (l == 0) out[b*Kc + k] = acc;
    }
}

// ---------------- host orchestration ----------------------------------------
extern "C" void kernel_launch(void* const* d_in, const int* in_sizes, int n_in,
                              void* d_out, int out_size){
    const int*   seqs  = (const int*)  d_in[0];
    const int*   idxs  = (const int*)  d_in[1];
    const float* emb   = (const float*)d_in[2];
    const float* pos   = (const float*)d_in[3];
    const float* blkg  = (const float*)d_in[4];
    const float* blkb  = (const float*)d_in[5];
    const float* in_w  = (const float*)d_in[6];
    const float* in_b  = (const float*)d_in[7];
    const float* convw = (const float*)d_in[8];
    const float* convb = (const float*)d_in[9];
    const float* xp_w  = (const float*)d_in[10];
    const float* xp_b  = (const float*)d_in[11];
    const float* A_log = (const float*)d_in[12];
    const float* Dp    = (const float*)d_in[13];
    const float* out_w = (const float*)d_in[14];
    const float* out_b = (const float*)d_in[15];
    const float* ilg   = (const float*)d_in[16];
    const float* ilb   = (const float*)d_in[17];
    const float* flg   = (const float*)d_in[18];
    const float* flb   = (const float*)d_in[19];
    float* logits = (float*)d_out;

    float *x,*ln,*xz,*xc,*xs,*ssm,*yc,*gate;
    cudaGetSymbolAddress((void**)&x,    g_x);
    cudaGetSymbolAddress((void**)&ln,   g_ln);
    cudaGetSymbolAddress((void**)&xz,   g_xz);
    cudaGetSymbolAddress((void**)&xc,   g_xc);
    cudaGetSymbolAddress((void**)&xs,   g_xsum);
    cudaGetSymbolAddress((void**)&ssm,  g_ssm);
    cudaGetSymbolAddress((void**)&yc,   g_yc);
    cudaGetSymbolAddress((void**)&gate, g_gate);

    embed_kernel<<<(BLr*(Hsz/4) + 255)/256, 256>>>(seqs, emb, pos, x);

    for (int blk = 0; blk < NBsz; blk++){
        ln128_kernel<<<BLr/4, 128>>>(x, blkg + blk*Hsz, blkb + blk*Hsz, ln);

        gemm_tf32_kernel<<<dim3(BLr/GBM, (2*Esz)/GBN), 256>>>(
            ln, in_w + (long)blk*Hsz*2*Esz, in_b + blk*2*Esz, xz,
            BLr, Hsz, 2*Esz, nullptr, nullptr);

        conv_kernel<<<BLr/4, 128>>>(xz, convw + blk*Esz*3, convb + blk*Esz, xc, xs);

        gemm_tf32_kernel<<<dim3(BLr/GBM, (3*Ssz)/GBN), 256>>>(
            xc, xp_w + (long)blk*Esz*3*Ssz, xp_b + blk*3*Ssz, ssm,
            BLr, Esz, 3*Ssz, nullptr, nullptr);

        scan_kernel<<<Bsz, 256>>>(ssm, xs, A_log + blk*Ssz, yc);

        gate_kernel<<<BLr/4, 128>>>(xc, yc, xz, Dp + blk*Esz, ilg + blk*Esz, ilb + blk*Esz, gate);

        gemm_tf32_kernel<<<dim3(BLr/GBM, Hsz/GBN), 256>>>(
            gate, out_w + (long)blk*Esz*Hsz, out_b + blk*Hsz, x,
            BLr, Esz, Hsz, x, seqs);
    }

    final_kernel<<<Bsz, Hsz>>>(x, flg, flb, idxs, emb, logits);
}

// round 12
// speedup vs baseline: 1.3849x; 1.0297x over previous
#include <cuda_runtime.h>
#include <cuda_bf16.h>
#include <cstdint>

// Problem constants
#define Bsz 64
#define Lsz 200
#define Hsz 128
#define Ssz 64
#define Esz 256
#define NBsz 2
#define Kc  101
#define BLr (Bsz*Lsz)   // 12800 rows

// ---------------- scratch (device globals; no allocation allowed) -----------
__device__ float g_x   [BLr*Hsz];
__device__ float g_ln  [BLr*Hsz];
__device__ float g_xz  [BLr*2*Esz];
__device__ float g_xc  [BLr*Esz];
__device__ float g_xsum[BLr];
__device__ float g_ssm [BLr*3*Ssz];
__device__ float g_yc  [BLr];
__device__ float g_gate[BLr*Esz];

// ---------------- helpers ---------------------------------------------------
__device__ __forceinline__ float sigmoidf_(float x){ return 1.f/(1.f+__expf(-x)); }
__device__ __forceinline__ float siluf_(float x){ return x*sigmoidf_(x); }
__device__ __forceinline__ float softplusf_(float x){ return x>20.f ? x : log1pf(__expf(x)); }

template<int NW>
__device__ __forceinline__ float block_sum(float v, float* sm){
    #pragma unroll
    for (int o=16;o;o>>=1) v += __shfl_xor_sync(0xffffffffu, v, o);
    __syncthreads();
    if ((threadIdx.x&31)==0) sm[threadIdx.x>>5] = v;
    __syncthreads();
    float s = 0.f;
    #pragma unroll
    for (int i=0;i<NW;i++) s += sm[i];
    return s;
}

__device__ __forceinline__ float warp_sum(float v){
    #pragma unroll
    for (int o=16;o;o>>=1) v += __shfl_xor_sync(0xffffffffu, v, o);
    return v;
}

// pack two consecutive fp32 into bf16x2 hi + bf16x2 lo words
__device__ __forceinline__ void packbf(float2 v, uint32_t& hi, uint32_t& lo){
    __nv_bfloat162 h2 = __float22bfloat162_rn(v);
    float2 hf = __bfloat1622float2(h2);
    __nv_bfloat162 l2 = __float22bfloat162_rn(make_float2(v.x-hf.x, v.y-hf.y));
    hi = *reinterpret_cast<uint32_t*>(&h2);
    lo = *reinterpret_cast<uint32_t*>(&l2);
}

__device__ __forceinline__ void mma16n8k16bf(float* c, const uint32_t* a, const uint32_t* b){
    asm volatile("mma.sync.aligned.m16n8k16.row.col.f32.bf16.bf16.f32 "
        "{%0,%1,%2,%3}, {%4,%5,%6,%7}, {%8,%9}, {%0,%1,%2,%3};"
        : "+f"(c[0]),"+f"(c[1]),"+f"(c[2]),"+f"(c[3])
        : "r"(a[0]),"r"(a[1]),"r"(a[2]),"r"(a[3]), "r"(b[0]),"r"(b[1]));
}

#define LDSM4(r, addr) \
    asm volatile("ldmatrix.sync.aligned.m8n8.x4.shared.b16 {%0,%1,%2,%3}, [%4];" \
        : "=r"((r)[0]),"=r"((r)[1]),"=r"((r)[2]),"=r"((r)[3]) : "r"(addr))

#define LDSM4T(r, addr) \
    asm volatile("ldmatrix.sync.aligned.m8n8.x4.trans.shared.b16 {%0,%1,%2,%3}, [%4];" \
        : "=r"((r)[0]),"=r"((r)[1]),"=r"((r)[2]),"=r"((r)[3]) : "r"(addr))

// ---------------- embed: x = (item_emb[seq] + pos) * mask, float4 ----------
__global__ void embed_kernel(const int* __restrict__ seqs, const float* __restrict__ emb,
                             const float* __restrict__ pos, float* __restrict__ x){
    int idx = blockIdx.x*blockDim.x + threadIdx.x;
    if (idx >= BLr*(Hsz/4)) return;
    int h4 = (idx & 31) * 4;
    int bl = idx >> 5;
    int t  = bl % Lsz;
    int s  = seqs[bl];
    float4 o;
    if (s){
        float4 e = *(const float4*)(emb + (long)s*Hsz + h4);
        float4 p = *(const float4*)(pos + t*Hsz + h4);
        o = make_float4(e.x+p.x, e.y+p.y, e.z+p.z, e.w+p.w);
    } else {
        o = make_float4(0.f,0.f,0.f,0.f);
    }
    *(float4*)(x + (long)bl*Hsz + h4) = o;
}

// ---------------- layernorm H=128, warp-per-row -----------------------------
__global__ void ln128_kernel(const float* __restrict__ x, const float* __restrict__ g,
                             const float* __restrict__ b, float* __restrict__ out){
    int row  = blockIdx.x*4 + (threadIdx.x >> 5);
    int lane = threadIdx.x & 31;
    float4 v = *(const float4*)(x + (long)row*Hsz + lane*4);
    float m = warp_sum(v.x + v.y + v.z + v.w) * (1.f/Hsz);
    float4 d = make_float4(v.x-m, v.y-m, v.z-m, v.w-m);
    float var = warp_sum(d.x*d.x + d.y*d.y + d.z*d.z + d.w*d.w) * (1.f/Hsz);
    float inv = rsqrtf(var + 1e-5f);
    float4 gg = *(const float4*)(g + lane*4);
    float4 bb = *(const float4*)(b + lane*4);
    float4 o;
    o.x = d.x*inv*gg.x + bb.x;
    o.y = d.y*inv*gg.y + bb.y;
    o.z = d.z*inv*gg.z + bb.z;
    o.w = d.w*inv*gg.w + bb.w;
    *(float4*)(out + (long)row*Hsz + lane*4) = o;
}

// ---------------- bf16 hi/lo GEMM with ldmatrix fragments -------------------
// BM=128, BN=64, BK=32, 256 threads = 8 warps (4M x 2N), warp tile 32x32.
// SMEM: A row-major [m][k] bf16 (stride 40), B row-major [k][n] bf16 (stride 72).
// If resid != nullptr: out = (resid + (A@W+b)) * (seqs[row]!=0)
#define GBM 128
#define GBN 64
#define GBK 32
#define ASTRB 40    // A row stride in bf16 (80 B, 16B-aligned, LDSM conflict-free)
#define BSTRB 72    // B row stride in bf16 (144 B, 16B-aligned, LDSM conflict-free)

__global__ __launch_bounds__(256) void gemm_tf32_kernel(
        const float* __restrict__ A, const float* __restrict__ W,
        const float* __restrict__ bias, float* __restrict__ C,
        int M, int Kd, int N,
        const float* __restrict__ resid, const int* __restrict__ mask_seq){
    __shared__ uint16_t Ah[GBM][ASTRB], Al[GBM][ASTRB];   // 2 x 10.0 KB
    __shared__ uint16_t Bh[GBK][BSTRB], Bl[GBK][BSTRB];   // 2 x 4.5 KB
    int tid  = threadIdx.x;
    int lane = tid & 31;
    int w    = tid >> 5;
    int warpM = w >> 1;
    int warpN = w & 1;
    int g  = lane >> 2;
    int tg = lane & 3;
    int bm = blockIdx.x * GBM;
    int bn = blockIdx.y * GBN;

    // global-load mapping
    int arow = tid >> 3;             // 0..31 (+32r)
    int acol = (tid & 7) * 4;        // K offset 0..28
    int brow = tid >> 3;             // k row 0..31
    int bncol = (tid & 7) * 8;       // n offset 0..56

    // LDSM lane addressing
    uint32_t sAh = (uint32_t)__cvta_generic_to_shared(&Ah[0][0]);
    uint32_t sAl = (uint32_t)__cvta_generic_to_shared(&Al[0][0]);
    uint32_t sBh = (uint32_t)__cvta_generic_to_shared(&Bh[0][0]);
    uint32_t sBl = (uint32_t)__cvta_generic_to_shared(&Bl[0][0]);
    int rl   = (lane & 7) + ((lane >> 3) & 1) * 8;   // 0..15
    int sel  = (lane >> 4) & 1;
    uint32_t aOff = (uint32_t)((warpM*32 + rl) * (ASTRB*2) + sel * 16);          // + mi*16 rows + k16*32B
    uint32_t bOff = (uint32_t)(rl * (BSTRB*2) + (warpN*32 + sel*8) * 2);         // + pair*32B + k16*16 rows

    float acc[2][4][4];
    #pragma unroll
    for (int mi=0;mi<2;mi++)
        #pragma unroll
        for (int ni=0;ni<4;ni++)
            #pragma unroll
            for (int c=0;c<4;c++) acc[mi][ni][c]=0.f;

    // prefetch tile 0
    float4 pa[4], pb0, pb1;
    #pragma unroll
    for (int r=0;r<4;r++)
        pa[r] = *(const float4*)(A + (long)(bm + arow + 32*r)*Kd + acol);
    pb0 = *(const float4*)(W + (long)brow*N + bn + bncol);
    pb1 = *(const float4*)(W + (long)brow*N + bn + bncol + 4);

    for (int kt = 0; kt < Kd; kt += GBK){
        // pack + commit prefetched tile to SMEM (plain bf16 element layout)
        #pragma unroll
        for (int r=0;r<4;r++){
            uint32_t h0,l0,h1,l1;
            packbf(make_float2(pa[r].x, pa[r].y), h0, l0);
            packbf(make_float2(pa[r].z, pa[r].w), h1, l1);
            uint32_t* dh = (uint32_t*)&Ah[arow+32*r][acol];
            uint32_t* dl = (uint32_t*)&Al[arow+32*r][acol];
            dh[0]=h0; dh[1]=h1;
            dl[0]=l0; dl[1]=l1;
        }
        {
            uint32_t h[4], l[4];
            packbf(make_float2(pb0.x, pb0.y), h[0], l[0]);
            packbf(make_float2(pb0.z, pb0.w), h[1], l[1]);
            packbf(make_float2(pb1.x, pb1.y), h[2], l[2]);
            packbf(make_float2(pb1.z, pb1.w), h[3], l[3]);
            *(uint4*)&Bh[brow][bncol] = make_uint4(h[0],h[1],h[2],h[3]);
            *(uint4*)&Bl[brow][bncol] = make_uint4(l[0],l[1],l[2],l[3]);
        }
        __syncthreads();

        // prefetch next tile
        if (kt + GBK < Kd){
            #pragma unroll
            for (int r=0;r<4;r++)
                pa[r] = *(const float4*)(A + (long)(bm + arow + 32*r)*Kd + kt + GBK + acol);
            pb0 = *(const float4*)(W + (long)(kt + GBK + brow)*N + bn + bncol);
            pb1 = *(const float4*)(W + (long)(kt + GBK + brow)*N + bn + bncol + 4);
        }

        #pragma unroll
        for (int k16 = 0; k16 < GBK/16; k16++){
            uint32_t ah[2][4], al[2][4];
            LDSM4(ah[0], sAh + aOff + k16*32);
            LDSM4(ah[1], sAh + aOff + 16*(ASTRB*2) + k16*32);
            LDSM4(al[0], sAl + aOff + k16*32);
            LDSM4(al[1], sAl + aOff + 16*(ASTRB*2) + k16*32);
            uint32_t rb0[4], rb1[4], rb2[4], rb3[4];
            LDSM4T(rb0, sBh + bOff + k16*16*(BSTRB*2));
            LDSM4T(rb1, sBh + bOff + 32 + k16*16*(BSTRB*2));
            LDSM4T(rb2, sBl + bOff + k16*16*(BSTRB*2));
            LDSM4T(rb3, sBl + bOff + 32 + k16*16*(BSTRB*2));
            uint32_t bh[4][2], bl[4][2];
            bh[0][0]=rb0[0]; bh[0][1]=rb0[1]; bh[1][0]=rb0[2]; bh[1][1]=rb0[3];
            bh[2][0]=rb1[0]; bh[2][1]=rb1[1]; bh[3][0]=rb1[2]; bh[3][1]=rb1[3];
            bl[0][0]=rb2[0]; bl[0][1]=rb2[1]; bl[1][0]=rb2[2]; bl[1][1]=rb2[3];
            bl[2][0]=rb3[0]; bl[2][1]=rb3[1]; bl[3][0]=rb3[2]; bl[3][1]=rb3[3];
            #pragma unroll
            for (int mi=0;mi<2;mi++)
                #pragma unroll
                for (int ni=0;ni<4;ni++){
                    mma16n8k16bf(acc[mi][ni], ah[mi], bh[ni]);
                    mma16n8k16bf(acc[mi][ni], ah[mi], bl[ni]);
                    mma16n8k16bf(acc[mi][ni], al[mi], bh[ni]);
                }
        }
        __syncthreads();
    }

    // epilogue
    #pragma unroll
    for (int mi=0;mi<2;mi++){
        int r0 = bm + warpM*32 + mi*16 + g;
        #pragma unroll
        for (int ni=0;ni<4;ni++){
            int col = bn + warpN*32 + ni*8 + 2*tg;
            float b0 = bias[col], b1 = bias[col+1];
            float v00 = acc[mi][ni][0] + b0, v01 = acc[mi][ni][1] + b1;
            float v10 = acc[mi][ni][2] + b0, v11 = acc[mi][ni][3] + b1;
            if (resid){
                float m0 = (mask_seq[r0]   != 0) ? 1.f : 0.f;
                float m1 = (mask_seq[r0+8] != 0) ? 1.f : 0.f;
                const float* rr0 = resid + (long)r0*N + col;
                const float* rr1 = resid + (long)(r0+8)*N + col;
                v00 = (rr0[0] + v00)*m0; v01 = (rr0[1] + v01)*m0;
                v10 = (rr1[0] + v10)*m1; v11 = (rr1[1] + v11)*m1;
            }
            *(float2*)(C + (long)r0*N + col)     = make_float2(v00, v01);
            *(float2*)(C + (long)(r0+8)*N + col) = make_float2(v10, v11);
        }
    }
}

// ---------------- depthwise conv(k=3,pad=1)+silu+row-sum, warp-per-row ------
__global__ void conv_kernel(const float* __restrict__ xz, const float* __restrict__ cw,
                            const float* __restrict__ cb, float* __restrict__ xc,
                            float* __restrict__ xsum){
    int row  = blockIdx.x*4 + (threadIdx.x >> 5);
    int lane = threadIdx.x & 31;
    int t = row % Lsz;
    int e0 = lane*8;
    const float* rp = xz + (long)row*(2*Esz) + e0;
    float4 c0a = *(const float4*)(rp);
    float4 c0b = *(const float4*)(rp + 4);
    float4 cma, cmb, cpa, cpb;
    if (t > 0){ cma = *(const float4*)(rp - 2*Esz); cmb = *(const float4*)(rp - 2*Esz + 4); }
    else      { cma = make_float4(0.f,0.f,0.f,0.f); cmb = cma; }
    if (t < Lsz-1){ cpa = *(const float4*)(rp + 2*Esz); cpb = *(const float4*)(rp + 2*Esz + 4); }
    else          { cpa = make_float4(0.f,0.f,0.f,0.f); cpb = cpa; }
    float wreg[24];
    #pragma unroll
    for (int i=0;i<6;i++)
        *(float4*)(wreg + i*4) = *(const float4*)(cw + e0*3 + i*4);
    float breg[8];
    *(float4*)(breg)     = *(const float4*)(cb + e0);
    *(float4*)(breg + 4) = *(const float4*)(cb + e0 + 4);

    float xm[8] = {cma.x,cma.y,cma.z,cma.w, cmb.x,cmb.y,cmb.z,cmb.w};
    float x0[8] = {c0a.x,c0a.y,c0a.z,c0a.w, c0b.x,c0b.y,c0b.z,c0b.w};
    float xp[8] = {cpa.x,cpa.y,cpa.z,cpa.w, cpb.x,cpb.y,cpb.z,cpb.w};
    float s[8];
    float tot = 0.f;
    #pragma unroll
    for (int i=0;i<8;i++){
        float v = fmaf(xm[i], wreg[i*3+0], fmaf(x0[i], wreg[i*3+1], fmaf(xp[i], wreg[i*3+2], breg[i])));
        s[i] = siluf_(v);
        tot += s[i];
    }
    tot = warp_sum(tot);
    if (lane == 0) xsum[row] = tot;
    float* op = xc + (long)row*Esz + e0;
    *(float4*)(op)     = make_float4(s[0],s[1],s[2],s[3]);
    *(float4*)(op + 4) = make_float4(s[4],s[5],s[6],s[7]);
}

// ---------------- sequential SSM scan (state collapsed to [B,S]) ------------
__global__ __launch_bounds__(256) void scan_kernel(
        const float* __restrict__ ssm, const float* __restrict__ xsum,
        const float* __restrict__ A_log, float* __restrict__ yc){
    __shared__ float A_s[Ssz], h_s[Ssz], dB_s[Ssz], C_s[Ssz], delta_s[Ssz], prod_s[Ssz];
    __shared__ float xs_sh;
    int b = blockIdx.x;
    int tid = threadIdx.x;          // 256
    int i = tid >> 2;
    int q = tid & 3;

    if (tid < Ssz){
        A_s[tid] = -__expf(fminf(fmaxf(A_log[tid], -5.f), 5.f));
        h_s[tid] = 0.f;
    }
    __syncthreads();
    float Areg[16];
    #pragma unroll
    for (int jj=0;jj<16;jj++) Areg[jj] = A_s[q*16+jj];

    const float* srow = ssm + (long)b*Lsz*(3*Ssz);
    float nd=0.f, nb=0.f, nc=0.f, nxs=0.f;
    if (tid < Ssz){ nd = srow[tid]; nb = srow[Ssz+tid]; nc = srow[2*Ssz+tid]; }
    if (tid == 0) nxs = xsum[b*Lsz];

    for (int t=0; t<Lsz; t++){
        if (tid < Ssz){
            float d = softplusf_(nd);
            delta_s[tid] = d;
            dB_s[tid] = d * nb;
            C_s[tid]  = nc;
        }
        if (tid == 0) xs_sh = nxs;
        __syncthreads();
        if (t+1 < Lsz){
            const float* nr = srow + (long)(t+1)*(3*Ssz);
            if (tid < Ssz){ nd = nr[tid]; nb = nr[Ssz+tid]; nc = nr[2*Ssz+tid]; }
            if (tid == 0) nxs = xsum[b*Lsz + t + 1];
        }
        float di = delta_s[i];
        float partial = 0.f;
        #pragma unroll
        for (int jj=0;jj<16;jj++){
            int j = q*16 + jj;
            float w = __expf(fmaxf(di * Areg[jj], -10.f));
            partial = fmaf(w, h_s[j], partial);
        }
        partial += __shfl_xor_sync(0xffffffffu, partial, 1);
        partial += __shfl_xor_sync(0xffffffffu, partial, 2);
        float hn = 0.f, pr = 0.f;
        if (q == 0){
            hn = partial + dB_s[i]*xs_sh;
            hn = fminf(fmaxf(hn, -100.f), 100.f);
            pr = hn * C_s[i];
        }
        __syncthreads();
        if (q == 0){ h_s[i] = hn; prod_s[i] = pr; }
        __syncthreads();
        if (tid < 32){
            float v = prod_s[tid] + prod_s[tid+32];
            #pragma unroll
            for (int o=16;o;o>>=1) v += __shfl_xor_sync(0xffffffffu, v, o);
            if (tid == 0) yc[b*Lsz + t] = v;
        }
    }
}

// ---------------- y = LN_E(yc + D*xc) * silu(z), warp-per-row ---------------
__global__ void gate_kernel(const float* __restrict__ xc, const float* __restrict__ yc,
                            const float* __restrict__ xz, const float* __restrict__ Dp,
                            const float* __restrict__ ig, const float* __restrict__ ib,
                            float* __restrict__ out){
    int row  = blockIdx.x*4 + (threadIdx.x >> 5);
    int lane = threadIdx.x & 31;
    float ycr = yc[row];
    float4 a0 = *(const float4*)(xc + (long)row*Esz + lane*8);
    float4 a1 = *(const float4*)(xc + (long)row*Esz + lane*8 + 4);
    float4 d0 = *(const float4*)(Dp + lane*8);
    float4 d1 = *(const float4*)(Dp + lane*8 + 4);
    float v[8];
    v[0]=ycr+d0.x*a0.x; v[1]=ycr+d0.y*a0.y; v[2]=ycr+d0.z*a0.z; v[3]=ycr+d0.w*a0.w;
    v[4]=ycr+d1.x*a1.x; v[5]=ycr+d1.y*a1.y; v[6]=ycr+d1.z*a1.z; v[7]=ycr+d1.w*a1.w;
    float s = 0.f;
    #pragma unroll
    for (int i=0;i<8;i++) s += v[i];
    float m = warp_sum(s) * (1.f/Esz);
    float vs = 0.f;
    #pragma unroll
    for (int i=0;i<8;i++){ v[i] -= m; vs += v[i]*v[i]; }
    float var = warp_sum(vs) * (1.f/Esz);
    float inv = rsqrtf(var + 1e-5f);
    float4 g0 = *(const float4*)(ig + lane*8);
    float4 g1 = *(const float4*)(ig + lane*8 + 4);
    float4 b0 = *(const float4*)(ib + lane*8);
    float4 b1 = *(const float4*)(ib + lane*8 + 4);
    float4 z0 = *(const float4*)(xz + (long)row*(2*Esz) + Esz + lane*8);
    float4 z1 = *(const float4*)(xz + (long)row*(2*Esz) + Esz + lane*8 + 4);
    float4 o0, o1;
    o0.x = (v[0]*inv*g0.x + b0.x) * siluf_(z0.x);
    o0.y = (v[1]*inv*g0.y + b0.y) * siluf_(z0.y);
    o0.z = (v[2]*inv*g0.z + b0.z) * siluf_(z0.z);
    o0.w = (v[3]*inv*g0.w + b0.w) * siluf_(z0.w);
    o1.x = (v[4]*inv*g1.x + b1.x) * siluf_(z1.x);
    o1.y = (v[5]*inv*g1.y + b1.y) * siluf_(z1.y);
    o1.z = (v[6]*inv*g1.z + b1.z) * siluf_(z1.z);
    o1.w = (v[7]*inv*g1.w + b1.w) * siluf_(z1.w);
    *(float4*)(out + (long)row*Esz + lane*8)     = o0;
    *(float4*)(out + (long)row*Esz + lane*8 + 4) = o1;
}

// ---------------- final LN (last step only) + candidate logits --------------
__global__ void final_kernel(const float* __restrict__ x, const float* __restrict__ fg,
                             const float* __restrict__ fb, const int* __restrict__ idxs,
                             const float* __restrict__ emb, float* __restrict__ out){
    __shared__ float sm[4];
    __shared__ float xf[Hsz];
    int b = blockIdx.x;
    int tid = threadIdx.x;  // 128
    const float* xr = x + (long)(b*Lsz + Lsz-1)*Hsz;
    float v = xr[tid];
    float m = block_sum<4>(v, sm) * (1.f/Hsz);
    float d = v - m;
    float var = block_sum<4>(d*d, sm) * (1.f/Hsz);
    float inv = rsqrtf(var + 1e-5f);
    xf[tid] = d*inv*fg[tid] + fb[tid];
    __syncthreads();
    int w = tid >> 5, l = tid & 31;
    for (int k = w; k < Kc; k += 4){
        int idx = idxs[b*Kc + k];
        const float* er = emb + (long)idx*Hsz;
        float acc = 0.f;
        #pragma unroll
        for (int r=0;r<4;r++) acc = fmaf(xf[l+32*r], er[l+32*r], acc);
        #pragma unroll
        for (int o=16;o;o>>=1) acc += __shfl_xor_sync(0xffffffffu, acc, o);
        if (l == 0) out[b*Kc + k] = acc;
    }
}

// ---------------- host orchestration ----------------------------------------
extern "C" void kernel_launch(void* const* d_in, const int* in_sizes, int n_in,
                              void* d_out, int out_size){
    const int*   seqs  = (const int*)  d_in[0];
    const int*   idxs  = (const int*)  d_in[1];
    const float* emb   = (const float*)d_in[2];
    const float* pos   = (const float*)d_in[3];
    const float* blkg  = (const float*)d_in[4];
    const float* blkb  = (const float*)d_in[5];
    const float* in_w  = (const float*)d_in[6];
    const float* in_b  = (const float*)d_in[7];
    const float* convw = (const float*)d_in[8];
    const float* convb = (const float*)d_in[9];
    const float* xp_w  = (const float*)d_in[10];
    const float* xp_b  = (const float*)d_in[11];
    const float* A_log = (const float*)d_in[12];
    const float* Dp    = (const float*)d_in[13];
    const float* out_w = (const float*)d_in[14];
    const float* out_b = (const float*)d_in[15];
    const float* ilg   = (const float*)d_in[16];
    const float* ilb   = (const float*)d_in[17];
    const float* flg   = (const float*)d_in[18];
    const float* flb   = (const float*)d_in[19];
    float* logits = (float*)d_out;

    float *x,*ln,*xz,*xc,*xs,*ssm,*yc,*gate;
    cudaGetSymbolAddress((void**)&x,    g_x);
    cudaGetSymbolAddress((void**)&ln,   g_ln);
    cudaGetSymbolAddress((void**)&xz,   g_xz);
    cudaGetSymbolAddress((void**)&xc,   g_xc);
    cudaGetSymbolAddress((void**)&xs,   g_xsum);
    cudaGetSymbolAddress((void**)&ssm,  g_ssm);
    cudaGetSymbolAddress((void**)&yc,   g_yc);
    cudaGetSymbolAddress((void**)&gate, g_gate);

    embed_kernel<<<(BLr*(Hsz/4) + 255)/256, 256>>>(seqs, emb, pos, x);

    for (int blk = 0; blk < NBsz; blk++){
        ln128_kernel<<<BLr/4, 128>>>(x, blkg + blk*Hsz, blkb + blk*Hsz, ln);

        gemm_tf32_kernel<<<dim3(BLr/GBM, (2*Esz)/GBN), 256>>>(
            ln, in_w + (long)blk*Hsz*2*Esz, in_b + blk*2*Esz, xz,
            BLr, Hsz, 2*Esz, nullptr, nullptr);

        conv_kernel<<<BLr/4, 128>>>(xz, convw + blk*Esz*3, convb + blk*Esz, xc, xs);

        gemm_tf32_kernel<<<dim3(BLr/GBM, (3*Ssz)/GBN), 256>>>(
            xc, xp_w + (long)blk*Esz*3*Ssz, xp_b + blk*3*Ssz, ssm,
            BLr, Esz, 3*Ssz, nullptr, nullptr);

        scan_kernel<<<Bsz, 256>>>(ssm, xs, A_log + blk*Ssz, yc);

        gate_kernel<<<BLr/4, 128>>>(xc, yc, xz, Dp + blk*Esz, ilg + blk*Esz, ilb + blk*Esz, gate);

        gemm_tf32_kernel<<<dim3(BLr/GBM, Hsz/GBN), 256>>>(
            gate, out_w + (long)blk*Esz*Hsz, out_b + blk*Hsz, x,
            BLr, Esz, Hsz, x, seqs);
    }

    final_kernel<<<Bsz, Hsz>>>(x, flg, flb, idxs, emb, logits);
}